// round 14
// baseline (speedup 1.0000x reference)
#include <cuda_runtime.h>
#include <cstdint>

#define N_NODES 500000
#define N_EDGES 1250000
#define IN_DIM  128
#define HID     64
#define N_GRAPHS 16384

#define AS_STR 36   // A plane stride (floats): frag bank = 4g+tg, conflict-free
#define WS_STR 72   // W plane stride (floats): frag bank = 8tg+g, conflict-free

#define SCH 1024
#define NB ((N_NODES + SCH - 1) / SCH)   // 489 scan blocks

// ---- scratch (static device globals: allocation-free rule) ----
__device__ float g_y  [(size_t)N_NODES * HID];   // layer input/output ping
__device__ float g_h  [(size_t)N_NODES * HID];   // final layer output
__device__ int   g_src[N_EDGES];
__device__ int   g_dst[N_EDGES];
__device__ int   g_batch[N_NODES];
__device__ int   g_rowptr[N_NODES + 1];
__device__ int   g_cursor[N_NODES];
__device__ int   g_csr[N_EDGES];
__device__ int   g_part[512];
__device__ int   g_partx[512];
__device__ float g_wh[5 * 64 * 64];              // pre-split W hi planes
__device__ float g_wl[5 * 64 * 64];              // pre-split W lo planes

// ---------------------------------------------------------------------------
// helpers
// ---------------------------------------------------------------------------
__device__ __forceinline__ float f2tf32(float x) {
    unsigned r;
    asm("cvt.rna.tf32.f32 %0, %1;" : "=r"(r) : "f"(x));
    return __uint_as_float(r);
}
__device__ __forceinline__ void split2(float x, unsigned& hi, unsigned& lo) {
    float h = f2tf32(x);
    float l = f2tf32(x - h);
    hi = __float_as_uint(h);
    lo = __float_as_uint(l);
}
__device__ __forceinline__ void mma_tf32(float& c0, float& c1, float& c2, float& c3,
                                         unsigned a0, unsigned a1, unsigned a2, unsigned a3,
                                         unsigned b0, unsigned b1) {
    asm volatile("mma.sync.aligned.m16n8k8.row.col.f32.tf32.tf32.f32 "
                 "{%0,%1,%2,%3}, {%4,%5,%6,%7}, {%8,%9}, {%0,%1,%2,%3};"
                 : "+f"(c0), "+f"(c1), "+f"(c2), "+f"(c3)
                 : "r"(a0), "r"(a1), "r"(a2), "r"(a3), "r"(b0), "r"(b1));
}
__device__ __forceinline__ void cp16(float* dst_smem, const float* src, bool pred) {
    unsigned d = (unsigned)__cvta_generic_to_shared(dst_smem);
    int sz = pred ? 16 : 0;
    asm volatile("cp.async.cg.shared.global [%0], [%1], 16, %2;"
                 :: "r"(d), "l"(src), "r"(sz));
}
__device__ __forceinline__ void cp_commit() { asm volatile("cp.async.commit_group;"); }
__device__ __forceinline__ void cp_wait(int n) {
    switch (n) {
        case 0: asm volatile("cp.async.wait_group 0;"); break;
        case 1: asm volatile("cp.async.wait_group 1;"); break;
        case 2: asm volatile("cp.async.wait_group 2;"); break;
        default: asm volatile("cp.async.wait_group 3;"); break;
    }
}

// ---------------------------------------------------------------------------
// prep: detect int32 vs int64 indices, convert to int32 scratch.
// Word (N_NODES-1) is ODD: int64 layout -> high half = 0; int32 -> max gid != 0.
// ---------------------------------------------------------------------------
__global__ void prep_kernel(const void* __restrict__ edge,
                            const void* __restrict__ batch) {
    const bool mode64 = (((const int*)batch)[N_NODES - 1] == 0);
    int t = blockIdx.x * blockDim.x + threadIdx.x;
    if (t < N_EDGES) {
        if (mode64) {
            g_src[t] = (int)((const long long*)edge)[t];
            g_dst[t] = (int)((const long long*)edge)[N_EDGES + t];
        } else {
            g_src[t] = ((const int*)edge)[t];
            g_dst[t] = ((const int*)edge)[N_EDGES + t];
        }
    }
    if (t < N_NODES) {
        g_batch[t] = mode64 ? (int)((const long long*)batch)[t]
                            : ((const int*)batch)[t];
    }
}

// ---- W pre-split: 5 matrices (w0b, w1a, w1b, w2a, w2b), each 64x64 --------
__global__ void wsplit_kernel(const float* __restrict__ w0b,
                              const float* __restrict__ w1a,
                              const float* __restrict__ w1b,
                              const float* __restrict__ w2a,
                              const float* __restrict__ w2b) {
    int t = blockIdx.x * blockDim.x + threadIdx.x;
    if (t >= 5 * 4096) return;
    int m = t >> 12, i = t & 4095;
    const float* W = (m == 0) ? w0b : (m == 1) ? w1a : (m == 2) ? w1b
                   : (m == 3) ? w2a : w2b;
    float x = W[i];
    float h = f2tf32(x);
    g_wh[t] = h;
    g_wl[t] = f2tf32(x - h);
}

// ---------------------------------------------------------------------------
// CSR build: histogram -> hierarchical exclusive scan -> placement.
// ---------------------------------------------------------------------------
__global__ void hist_kernel() {
    int e = blockIdx.x * blockDim.x + threadIdx.x;
    if (e < N_EDGES) atomicAdd(&g_cursor[g_dst[e]], 1);
}

__global__ __launch_bounds__(256) void scan1_kernel() {
    __shared__ int sm[256];
    int b = blockIdx.x, t = threadIdx.x;
    int base = b * SCH + t * 4;
    int s = 0;
    #pragma unroll
    for (int i = 0; i < 4; ++i)
        if (base + i < N_NODES) s += g_cursor[base + i];
    sm[t] = s;
    __syncthreads();
    for (int off = 128; off; off >>= 1) {
        if (t < off) sm[t] += sm[t + off];
        __syncthreads();
    }
    if (t == 0) g_part[b] = sm[0];
}

__global__ __launch_bounds__(512) void scan2_kernel() {
    __shared__ int sm[512];
    int t = threadIdx.x;
    int myv = (t < NB) ? g_part[t] : 0;
    sm[t] = myv;
    __syncthreads();
    for (int off = 1; off < 512; off <<= 1) {
        int v = (t >= off) ? sm[t - off] : 0;
        __syncthreads();
        sm[t] += v;
        __syncthreads();
    }
    if (t < NB) g_partx[t] = sm[t] - myv;     // exclusive
    if (t == 0) g_rowptr[N_NODES] = N_EDGES;
}

__global__ __launch_bounds__(256) void scan3_kernel() {
    __shared__ int sm[256];
    int b = blockIdx.x, t = threadIdx.x;
    int base = b * SCH + t * 4;
    int d[4];
    int s = 0;
    #pragma unroll
    for (int i = 0; i < 4; ++i) {
        d[i] = (base + i < N_NODES) ? g_cursor[base + i] : 0;
        s += d[i];
    }
    int myv = s;
    sm[t] = s;
    __syncthreads();
    for (int off = 1; off < 256; off <<= 1) {
        int v = (t >= off) ? sm[t - off] : 0;
        __syncthreads();
        sm[t] += v;
        __syncthreads();
    }
    int run = g_partx[b] + sm[t] - myv;
    #pragma unroll
    for (int i = 0; i < 4; ++i) {
        if (base + i < N_NODES) {
            g_rowptr[base + i] = run;
            g_cursor[base + i] = run;
        }
        run += d[i];
    }
}

__global__ void place_kernel() {
    int e = blockIdx.x * blockDim.x + threadIdx.x;
    if (e >= N_EDGES) return;
    int dgt = g_dst[e];
    int pos = atomicAdd(&g_cursor[dgt], 1);
    g_csr[pos] = g_src[e];
}

// ---------------------------------------------------------------------------
// Fused gather stage: U = relu( Y[node] + sum_{u->node} Y[u] + ba ), written
// straight into the two A smem chunks.  2 threads per row, 32 cols each
// (half h -> chunk h).  Result is pre-activated: mainloop needs no bias.
// ---------------------------------------------------------------------------
__device__ __forceinline__ void gather_stage(float* Ab, const float* __restrict__ Y,
                                             const float* __restrict__ ba,
                                             int rowBase, int tid) {
    int row  = tid >> 1;
    int half = tid & 1;
    int node = rowBase + row;
    float* dst = Ab + (size_t)half * 128 * AS_STR + (size_t)row * AS_STR;
    if (node < N_NODES) {
        float4 acc[8];
        const float4* yp = (const float4*)&Y[(size_t)node * 64 + half * 32];
        #pragma unroll
        for (int q = 0; q < 8; ++q) acc[q] = yp[q];
        int lo = g_rowptr[node], hi = g_rowptr[node + 1];
        for (int i = lo; i < hi; ++i) {
            const float4* sp = (const float4*)&g_y[0] + 0;  // placeholder avoid warn
            (void)sp;
            int srow = g_csr[i];
            const float4* vp = (const float4*)&Y[(size_t)srow * 64 + half * 32];
            #pragma unroll
            for (int q = 0; q < 8; ++q) {
                float4 v = vp[q];
                acc[q].x += v.x; acc[q].y += v.y;
                acc[q].z += v.z; acc[q].w += v.w;
            }
        }
        const float4* bp = (const float4*)&ba[half * 32];
        #pragma unroll
        for (int q = 0; q < 8; ++q) {
            float4 b = __ldg(&bp[q]);
            float4 o;
            o.x = fmaxf(acc[q].x + b.x, 0.f);
            o.y = fmaxf(acc[q].y + b.y, 0.f);
            o.z = fmaxf(acc[q].z + b.z, 0.f);
            o.w = fmaxf(acc[q].w + b.w, 0.f);
            *(float4*)&dst[q * 4] = o;
        }
    } else {
        #pragma unroll
        for (int q = 0; q < 8; ++q)
            *(float4*)&dst[q * 4] = make_float4(0.f, 0.f, 0.f, 0.f);
    }
}

// ---------------------------------------------------------------------------
// mma over one BK=32 chunk; A raw in smem (split at read, no bias);
// W pre-split hi/lo planes in smem.
// ---------------------------------------------------------------------------
__device__ __forceinline__ void mma_pre_chunk(const float* __restrict__ Ab,
                                              const float* __restrict__ Wh,
                                              const float* __restrict__ Wl,
                                              float c[2][4][4],
                                              int wrow, int wcol, int g, int tg) {
    #pragma unroll
    for (int kk = 0; kk < 32; kk += 8) {
        unsigned ah[2][4], al[2][4];
        #pragma unroll
        for (int i = 0; i < 2; ++i) {
            int r0 = wrow + 16 * i + g;
            split2(Ab[(r0    ) * AS_STR + kk + tg],     ah[i][0], al[i][0]);
            split2(Ab[(r0 + 8) * AS_STR + kk + tg],     ah[i][1], al[i][1]);
            split2(Ab[(r0    ) * AS_STR + kk + tg + 4], ah[i][2], al[i][2]);
            split2(Ab[(r0 + 8) * AS_STR + kk + tg + 4], ah[i][3], al[i][3]);
        }
        #pragma unroll
        for (int j = 0; j < 4; ++j) {
            int cc = wcol + 8 * j + g;
            unsigned bh0 = __float_as_uint(Wh[(kk + tg    ) * WS_STR + cc]);
            unsigned bh1 = __float_as_uint(Wh[(kk + tg + 4) * WS_STR + cc]);
            unsigned bl0 = __float_as_uint(Wl[(kk + tg    ) * WS_STR + cc]);
            unsigned bl1 = __float_as_uint(Wl[(kk + tg + 4) * WS_STR + cc]);
            #pragma unroll
            for (int i = 0; i < 2; ++i) {
                mma_tf32(c[i][j][0], c[i][j][1], c[i][j][2], c[i][j][3],
                         al[i][0], al[i][1], al[i][2], al[i][3], bh0, bh1);
                mma_tf32(c[i][j][0], c[i][j][1], c[i][j][2], c[i][j][3],
                         ah[i][0], ah[i][1], ah[i][2], ah[i][3], bl0, bl1);
                mma_tf32(c[i][j][0], c[i][j][1], c[i][j][2], c[i][j][3],
                         ah[i][0], ah[i][1], ah[i][2], ah[i][3], bh0, bh1);
            }
        }
    }
}

// raw-W variant (mm_first only)
__device__ __forceinline__ void mma_raw_chunk(const float* __restrict__ Ab,
                                              const float* __restrict__ Wk,
                                              float c[2][4][4],
                                              int wrow, int wcol, int g, int tg) {
    #pragma unroll
    for (int kk = 0; kk < 32; kk += 8) {
        unsigned ah[2][4], al[2][4];
        #pragma unroll
        for (int i = 0; i < 2; ++i) {
            int r0 = wrow + 16 * i + g;
            split2(Ab[(r0    ) * AS_STR + kk + tg],     ah[i][0], al[i][0]);
            split2(Ab[(r0 + 8) * AS_STR + kk + tg],     ah[i][1], al[i][1]);
            split2(Ab[(r0    ) * AS_STR + kk + tg + 4], ah[i][2], al[i][2]);
            split2(Ab[(r0 + 8) * AS_STR + kk + tg + 4], ah[i][3], al[i][3]);
        }
        #pragma unroll
        for (int j = 0; j < 4; ++j) {
            int cc = wcol + 8 * j + g;
            unsigned bh0, bl0, bh1, bl1;
            split2(Wk[(kk + tg    ) * WS_STR + cc], bh0, bl0);
            split2(Wk[(kk + tg + 4) * WS_STR + cc], bh1, bl1);
            #pragma unroll
            for (int i = 0; i < 2; ++i) {
                mma_tf32(c[i][j][0], c[i][j][1], c[i][j][2], c[i][j][3],
                         al[i][0], al[i][1], al[i][2], al[i][3], bh0, bh1);
                mma_tf32(c[i][j][0], c[i][j][1], c[i][j][2], c[i][j][3],
                         ah[i][0], ah[i][1], ah[i][2], ah[i][3], bl0, bl1);
                mma_tf32(c[i][j][0], c[i][j][1], c[i][j][2], c[i][j][3],
                         ah[i][0], ah[i][1], ah[i][2], ah[i][3], bh0, bh1);
            }
        }
    }
}

template<int K>
__device__ __forceinline__ void cp_chunk(float* Ab, const float* __restrict__ A,
                                         int rowBase, int ch, int tid) {
    #pragma unroll
    for (int s = 0; s < 4; ++s) {
        int idx = tid + s * 256;
        int row = idx >> 3;
        int kg  = (idx & 7) * 4;
        int gr  = rowBase + row;
        cp16(&Ab[(size_t)(ch * 128 + row) * AS_STR + kg],
             &A[(size_t)gr * K + ch * 32 + kg], gr < N_NODES);
    }
    cp_commit();
}

__device__ __forceinline__ void load_w_all(float* Ws, const float* __restrict__ W,
                                           int K, int tid) {
    for (int idx = tid; idx < K * 16; idx += 256) {
        int k  = idx >> 4;
        int cg = (idx & 15) * 4;
        *(float4*)&Ws[(size_t)k * WS_STR + cg] = *(const float4*)&W[(size_t)k * 64 + cg];
    }
}

// ---------------------------------------------------------------------------
// mm_first: Y = A[N,K] @ W[K,64]   (raw W, split at read, cp.async pipeline)
// ---------------------------------------------------------------------------
template<int K>
__global__ __launch_bounds__(256, 2) void mm_first(const float* __restrict__ A,
                                                   const float* __restrict__ W,
                                                   float* __restrict__ Y) {
    constexpr int NCH = K / 32;
    extern __shared__ float sm[];
    float* Ab = sm;
    float* Ws = sm + (size_t)NCH * 128 * AS_STR;

    const int tid  = threadIdx.x;
    const int lane = tid & 31;
    const int w    = tid >> 5;
    const int g    = lane >> 2;
    const int tg   = lane & 3;
    const int wrow = (w & 3) * 32;
    const int wcol = (w >> 2) * 32;
    const int rowBase = blockIdx.x * 128;
    float c[2][4][4] = {};

    load_w_all(Ws, W, K, tid);
    #pragma unroll
    for (int ch = 0; ch < NCH; ++ch)
        cp_chunk<K>(Ab, A, rowBase, ch, tid);

    #pragma unroll
    for (int ch = 0; ch < NCH; ++ch) {
        cp_wait(NCH - 1 - ch);
        __syncthreads();
        mma_raw_chunk(Ab + (size_t)ch * 128 * AS_STR,
                      Ws + (size_t)ch * 32 * WS_STR, c, wrow, wcol, g, tg);
    }

    #pragma unroll
    for (int i = 0; i < 2; ++i) {
        int r0 = rowBase + wrow + 16 * i + g;
        #pragma unroll
        for (int j = 0; j < 4; ++j) {
            int col = wcol + 8 * j + 2 * tg;
            if (r0 < N_NODES)
                *(float2*)&Y[(size_t)r0 * 64 + col] = make_float2(c[i][j][0], c[i][j][1]);
            if (r0 + 8 < N_NODES)
                *(float2*)&Y[(size_t)(r0 + 8) * 64 + col] = make_float2(c[i][j][2], c[i][j][3]);
        }
    }
}

// ---------------------------------------------------------------------------
// mm_chain_g: U = relu(gather(Y)+ba)  [fused, in smem];
//             T = relu(U @ Wb + bb)   [staged back to smem];
//             Yn = T @ Wa2.
// ---------------------------------------------------------------------------
__global__ __launch_bounds__(256, 2) void mm_chain_g(const float* __restrict__ Y,
                                                     const float* __restrict__ ba,
                                                     const float* __restrict__ bbv,
                                                     int mb, int ma,
                                                     float* __restrict__ Yn) {
    extern __shared__ float sm[];
    float* Ab  = sm;                                  // 2*128*AS_STR
    float* WbH = sm  + (size_t)2 * 128 * AS_STR;
    float* WbL = WbH + (size_t)64 * WS_STR;
    float* WaH = WbL + (size_t)64 * WS_STR;
    float* WaL = WaH + (size_t)64 * WS_STR;

    const int tid  = threadIdx.x;
    const int lane = tid & 31;
    const int w    = tid >> 5;
    const int g    = lane >> 2;
    const int tg   = lane & 3;
    const int wrow = (w & 3) * 32;
    const int wcol = (w >> 2) * 32;
    const int rowBase = blockIdx.x * 128;
    float c[2][4][4] = {};

    load_w_all(WbH, g_wh + (size_t)mb * 4096, 64, tid);
    load_w_all(WbL, g_wl + (size_t)mb * 4096, 64, tid);
    load_w_all(WaH, g_wh + (size_t)ma * 4096, 64, tid);
    load_w_all(WaL, g_wl + (size_t)ma * 4096, 64, tid);

    gather_stage(Ab, Y, ba, rowBase, tid);
    __syncthreads();

    // GEMM1: U @ Wb  (U pre-activated in smem)
    mma_pre_chunk(Ab, WbH, WbL, c, wrow, wcol, g, tg);
    mma_pre_chunk(Ab + (size_t)128 * AS_STR,
                  WbH + (size_t)32 * WS_STR, WbL + (size_t)32 * WS_STR,
                  c, wrow, wcol, g, tg);
    __syncthreads();   // A-buffers free

    // stage T = relu(c+bb) raw into A-buffer (chunk = warp's wcol group)
    {
        float* Tb = Ab + (size_t)(wcol >> 5) * 128 * AS_STR;
        #pragma unroll
        for (int i = 0; i < 2; ++i) {
            int ra = wrow + 16 * i + g;
            #pragma unroll
            for (int j = 0; j < 4; ++j) {
                int lc = 8 * j + 2 * tg;
                float2 b2 = __ldg((const float2*)&bbv[wcol + lc]);
                *(float2*)&Tb[(size_t)ra * AS_STR + lc] =
                    make_float2(fmaxf(c[i][j][0] + b2.x, 0.f),
                                fmaxf(c[i][j][1] + b2.y, 0.f));
                *(float2*)&Tb[(size_t)(ra + 8) * AS_STR + lc] =
                    make_float2(fmaxf(c[i][j][2] + b2.x, 0.f),
                                fmaxf(c[i][j][3] + b2.y, 0.f));
                c[i][j][0] = c[i][j][1] = c[i][j][2] = c[i][j][3] = 0.f;
            }
        }
    }
    __syncthreads();

    // GEMM2: T @ Wa2
    mma_pre_chunk(Ab, WaH, WaL, c, wrow, wcol, g, tg);
    mma_pre_chunk(Ab + (size_t)128 * AS_STR,
                  WaH + (size_t)32 * WS_STR, WaL + (size_t)32 * WS_STR,
                  c, wrow, wcol, g, tg);

    #pragma unroll
    for (int i = 0; i < 2; ++i) {
        int r0 = rowBase + wrow + 16 * i + g;
        #pragma unroll
        for (int j = 0; j < 4; ++j) {
            int col = wcol + 8 * j + 2 * tg;
            if (r0 < N_NODES)
                *(float2*)&Yn[(size_t)r0 * 64 + col] = make_float2(c[i][j][0], c[i][j][1]);
            if (r0 + 8 < N_NODES)
                *(float2*)&Yn[(size_t)(r0 + 8) * 64 + col] = make_float2(c[i][j][2], c[i][j][3]);
        }
    }
}

// ---------------------------------------------------------------------------
// mm_last_g: H = relu( relu(gather(Y)+ba) @ Wb + bb )
// ---------------------------------------------------------------------------
__global__ __launch_bounds__(256, 2) void mm_last_g(const float* __restrict__ Y,
                                                    const float* __restrict__ ba,
                                                    const float* __restrict__ bbv,
                                                    int mb,
                                                    float* __restrict__ H) {
    extern __shared__ float sm[];
    float* Ab  = sm;
    float* WbH = sm  + (size_t)2 * 128 * AS_STR;
    float* WbL = WbH + (size_t)64 * WS_STR;

    const int tid  = threadIdx.x;
    const int lane = tid & 31;
    const int w    = tid >> 5;
    const int g    = lane >> 2;
    const int tg   = lane & 3;
    const int wrow = (w & 3) * 32;
    const int wcol = (w >> 2) * 32;
    const int rowBase = blockIdx.x * 128;
    float c[2][4][4] = {};

    load_w_all(WbH, g_wh + (size_t)mb * 4096, 64, tid);
    load_w_all(WbL, g_wl + (size_t)mb * 4096, 64, tid);

    gather_stage(Ab, Y, ba, rowBase, tid);
    __syncthreads();

    mma_pre_chunk(Ab, WbH, WbL, c, wrow, wcol, g, tg);
    mma_pre_chunk(Ab + (size_t)128 * AS_STR,
                  WbH + (size_t)32 * WS_STR, WbL + (size_t)32 * WS_STR,
                  c, wrow, wcol, g, tg);

    #pragma unroll
    for (int i = 0; i < 2; ++i) {
        int r0 = rowBase + wrow + 16 * i + g;
        #pragma unroll
        for (int j = 0; j < 4; ++j) {
            int col = wcol + 8 * j + 2 * tg;
            float2 b2 = __ldg((const float2*)&bbv[col]);
            if (r0 < N_NODES)
                *(float2*)&H[(size_t)r0 * 64 + col] =
                    make_float2(fmaxf(c[i][j][0] + b2.x, 0.f),
                                fmaxf(c[i][j][1] + b2.y, 0.f));
            if (r0 + 8 < N_NODES)
                *(float2*)&H[(size_t)(r0 + 8) * 64 + col] =
                    make_float2(fmaxf(c[i][j][2] + b2.x, 0.f),
                                fmaxf(c[i][j][3] + b2.y, 0.f));
        }
    }
}

// ---------------------------------------------------------------------------
// Head: per-graph pooled sum + MLP.  One 64-thread block per graph.
// ---------------------------------------------------------------------------
__global__ __launch_bounds__(64) void head_kernel(const float* __restrict__ H,
                                                  const float* __restrict__ wh1,
                                                  const float* __restrict__ bh1,
                                                  const float* __restrict__ wh2,
                                                  const float* __restrict__ bh2,
                                                  float* __restrict__ out) {
    const int g = blockIdx.x;
    const int tid = threadIdx.x;
    __shared__ float pooled[64];
    __shared__ float red[64];
    __shared__ int range[2];
    if (tid < 2) {
        int target = g + tid;
        int lo = 0, hi = N_NODES;
        while (lo < hi) {
            int mid = (lo + hi) >> 1;
            if (g_batch[mid] < target) lo = mid + 1; else hi = mid;
        }
        range[tid] = lo;
    }
    __syncthreads();
    const int lo = range[0], hi = range[1];
    float p = 0.f;
    for (int i = lo; i < hi; ++i) p += H[(size_t)i * 64 + tid];
    pooled[tid] = p;
    __syncthreads();
    float u = bh1[tid];
    #pragma unroll
    for (int k = 0; k < 64; ++k) u += pooled[k] * wh1[k * 64 + tid];
    u = fmaxf(u, 0.f);
    red[tid] = u * wh2[tid];
    __syncthreads();
    if (tid < 32) red[tid] += red[tid + 32];
    __syncthreads();
    if (tid < 32) {
        float v = red[tid];
        #pragma unroll
        for (int off = 16; off; off >>= 1)
            v += __shfl_down_sync(0xffffffffu, v, off);
        if (tid == 0) out[g] = v + bh2[0];
    }
}

// ---------------------------------------------------------------------------
extern "C" void kernel_launch(void* const* d_in, const int* in_sizes, int n_in,
                              void* d_out, int out_size) {
    const float* x    = (const float*)d_in[0];
    const void*  edge = d_in[1];
    const void*  batc = d_in[2];
    const float* w0a = (const float*)d_in[3];
    const float* b0a = (const float*)d_in[4];
    const float* w0b = (const float*)d_in[5];
    const float* b0b = (const float*)d_in[6];
    const float* w1a = (const float*)d_in[7];
    const float* b1a = (const float*)d_in[8];
    const float* w1b = (const float*)d_in[9];
    const float* b1b = (const float*)d_in[10];
    const float* w2a = (const float*)d_in[11];
    const float* b2a = (const float*)d_in[12];
    const float* w2b = (const float*)d_in[13];
    const float* b2b = (const float*)d_in[14];
    const float* wh1 = (const float*)d_in[15];
    const float* bh1 = (const float*)d_in[16];
    const float* wh2 = (const float*)d_in[17];
    const float* bh2 = (const float*)d_in[18];

    float *yb, *hb;
    int  *curb;
    cudaGetSymbolAddress((void**)&yb,   g_y);
    cudaGetSymbolAddress((void**)&hb,   g_h);
    cudaGetSymbolAddress((void**)&curb, g_cursor);

    const int smFirst = (4 * 128 * AS_STR + 128 * WS_STR) * 4;     // 110592
    const int smChain = (2 * 128 * AS_STR + 4 * 64 * WS_STR) * 4;  // 110592
    const int smLast  = (2 * 128 * AS_STR + 2 * 64 * WS_STR) * 4;  //  73728
    cudaFuncSetAttribute(mm_first<128>, cudaFuncAttributeMaxDynamicSharedMemorySize, smFirst);
    cudaFuncSetAttribute(mm_chain_g,    cudaFuncAttributeMaxDynamicSharedMemorySize, smChain);
    cudaFuncSetAttribute(mm_last_g,     cudaFuncAttributeMaxDynamicSharedMemorySize, smLast);

    const int mmGrid  = (N_NODES + 127) / 128;
    const int edgGrid = (N_EDGES + 255) / 256;

    prep_kernel<<<edgGrid, 256>>>(edge, batc);
    wsplit_kernel<<<(5 * 4096 + 255) / 256, 256>>>(w0b, w1a, w1b, w2a, w2b);

    // CSR build
    cudaMemsetAsync(curb, 0, (size_t)N_NODES * sizeof(int));
    hist_kernel<<<edgGrid, 256>>>();
    scan1_kernel<<<NB, 256>>>();
    scan2_kernel<<<1, 512>>>();
    scan3_kernel<<<NB, 256>>>();
    place_kernel<<<edgGrid, 256>>>();

    // y0 = x @ w0a
    mm_first<128><<<mmGrid, 256, smFirst>>>(x, w0a, yb);

    // layer 0+1 fused-gather chains, layer 2 fused-gather last
    mm_chain_g<<<mmGrid, 256, smChain>>>(yb, b0a, b0b, 0, 1, hb);  // -> h (as y1)
    mm_chain_g<<<mmGrid, 256, smChain>>>(hb, b1a, b1b, 2, 3, yb);  // -> y2
    mm_last_g <<<mmGrid, 256, smLast >>>(yb, b2a, b2b, 4, hb);     // -> H

    head_kernel<<<N_GRAPHS, 64>>>(hb, wh1, bh1, wh2, bh2, (float*)d_out);
}

// round 15
// speedup vs baseline: 1.0960x; 1.0960x over previous
#include <cuda_runtime.h>
#include <cstdint>

#define N_NODES 500000
#define N_EDGES 1250000
#define IN_DIM  128
#define HID     64
#define N_GRAPHS 16384

#define AS_STR 36   // A plane stride (floats): frag bank = 4g+tg, conflict-free
#define WS_STR 72   // W plane stride (floats): frag bank = 8tg+g, conflict-free

#define SCH 1024
#define NB ((N_NODES + SCH - 1) / SCH)   // 489 scan blocks

// ---- scratch (static device globals: allocation-free rule) ----
__device__ float g_y  [(size_t)N_NODES * HID];   // y = h @ wa
__device__ float g_z  [(size_t)N_NODES * HID];   // z = y + agg (gather output)
__device__ float g_h  [(size_t)N_NODES * HID];   // final layer output
__device__ int   g_src[N_EDGES];
__device__ int   g_dst[N_EDGES];
__device__ int   g_batch[N_NODES];
__device__ int   g_rowptr[N_NODES + 1];
__device__ int   g_cursor[N_NODES];
__device__ int   g_csr[N_EDGES];
__device__ int   g_part[512];
__device__ int   g_partx[512];
__device__ float g_wh[5 * 64 * 64];              // pre-split W hi planes
__device__ float g_wl[5 * 64 * 64];              // pre-split W lo planes

// ---------------------------------------------------------------------------
// helpers
// ---------------------------------------------------------------------------
__device__ __forceinline__ float f2tf32(float x) {
    unsigned r;
    asm("cvt.rna.tf32.f32 %0, %1;" : "=r"(r) : "f"(x));
    return __uint_as_float(r);
}
__device__ __forceinline__ void split2(float x, unsigned& hi, unsigned& lo) {
    float h = f2tf32(x);
    float l = f2tf32(x - h);
    hi = __float_as_uint(h);
    lo = __float_as_uint(l);
}
__device__ __forceinline__ void mma_tf32(float& c0, float& c1, float& c2, float& c3,
                                         unsigned a0, unsigned a1, unsigned a2, unsigned a3,
                                         unsigned b0, unsigned b1) {
    asm volatile("mma.sync.aligned.m16n8k8.row.col.f32.tf32.tf32.f32 "
                 "{%0,%1,%2,%3}, {%4,%5,%6,%7}, {%8,%9}, {%0,%1,%2,%3};"
                 : "+f"(c0), "+f"(c1), "+f"(c2), "+f"(c3)
                 : "r"(a0), "r"(a1), "r"(a2), "r"(a3), "r"(b0), "r"(b1));
}
__device__ __forceinline__ void cp16(float* dst_smem, const float* src, bool pred) {
    unsigned d = (unsigned)__cvta_generic_to_shared(dst_smem);
    int sz = pred ? 16 : 0;
    asm volatile("cp.async.cg.shared.global [%0], [%1], 16, %2;"
                 :: "r"(d), "l"(src), "r"(sz));
}
__device__ __forceinline__ void cp_commit() { asm volatile("cp.async.commit_group;"); }
__device__ __forceinline__ void cp_wait(int n) {
    switch (n) {
        case 0: asm volatile("cp.async.wait_group 0;"); break;
        case 1: asm volatile("cp.async.wait_group 1;"); break;
        case 2: asm volatile("cp.async.wait_group 2;"); break;
        default: asm volatile("cp.async.wait_group 3;"); break;
    }
}

// ---------------------------------------------------------------------------
// prep: detect int32 vs int64 indices, convert to int32 scratch.
// Word (N_NODES-1) is ODD: int64 layout -> high half = 0; int32 -> max gid != 0.
// ---------------------------------------------------------------------------
__global__ void prep_kernel(const void* __restrict__ edge,
                            const void* __restrict__ batch) {
    const bool mode64 = (((const int*)batch)[N_NODES - 1] == 0);
    int t = blockIdx.x * blockDim.x + threadIdx.x;
    if (t < N_EDGES) {
        if (mode64) {
            g_src[t] = (int)((const long long*)edge)[t];
            g_dst[t] = (int)((const long long*)edge)[N_EDGES + t];
        } else {
            g_src[t] = ((const int*)edge)[t];
            g_dst[t] = ((const int*)edge)[N_EDGES + t];
        }
    }
    if (t < N_NODES) {
        g_batch[t] = mode64 ? (int)((const long long*)batch)[t]
                            : ((const int*)batch)[t];
    }
}

// ---- W pre-split: 5 matrices (w0b, w1a, w1b, w2a, w2b), each 64x64 --------
__global__ void wsplit_kernel(const float* __restrict__ w0b,
                              const float* __restrict__ w1a,
                              const float* __restrict__ w1b,
                              const float* __restrict__ w2a,
                              const float* __restrict__ w2b) {
    int t = blockIdx.x * blockDim.x + threadIdx.x;
    if (t >= 5 * 4096) return;
    int m = t >> 12, i = t & 4095;
    const float* W = (m == 0) ? w0b : (m == 1) ? w1a : (m == 2) ? w1b
                   : (m == 3) ? w2a : w2b;
    float x = W[i];
    float h = f2tf32(x);
    g_wh[t] = h;
    g_wl[t] = f2tf32(x - h);
}

// ---------------------------------------------------------------------------
// CSR build: histogram -> hierarchical exclusive scan -> placement.
// ---------------------------------------------------------------------------
__global__ void hist_kernel() {
    int e = blockIdx.x * blockDim.x + threadIdx.x;
    if (e < N_EDGES) atomicAdd(&g_cursor[g_dst[e]], 1);
}

__global__ __launch_bounds__(256) void scan1_kernel() {
    __shared__ int sm[256];
    int b = blockIdx.x, t = threadIdx.x;
    int base = b * SCH + t * 4;
    int s = 0;
    #pragma unroll
    for (int i = 0; i < 4; ++i)
        if (base + i < N_NODES) s += g_cursor[base + i];
    sm[t] = s;
    __syncthreads();
    for (int off = 128; off; off >>= 1) {
        if (t < off) sm[t] += sm[t + off];
        __syncthreads();
    }
    if (t == 0) g_part[b] = sm[0];
}

__global__ __launch_bounds__(512) void scan2_kernel() {
    __shared__ int sm[512];
    int t = threadIdx.x;
    int myv = (t < NB) ? g_part[t] : 0;
    sm[t] = myv;
    __syncthreads();
    for (int off = 1; off < 512; off <<= 1) {
        int v = (t >= off) ? sm[t - off] : 0;
        __syncthreads();
        sm[t] += v;
        __syncthreads();
    }
    if (t < NB) g_partx[t] = sm[t] - myv;     // exclusive
    if (t == 0) g_rowptr[N_NODES] = N_EDGES;
}

__global__ __launch_bounds__(256) void scan3_kernel() {
    __shared__ int sm[256];
    int b = blockIdx.x, t = threadIdx.x;
    int base = b * SCH + t * 4;
    int d[4];
    int s = 0;
    #pragma unroll
    for (int i = 0; i < 4; ++i) {
        d[i] = (base + i < N_NODES) ? g_cursor[base + i] : 0;
        s += d[i];
    }
    int myv = s;
    sm[t] = s;
    __syncthreads();
    for (int off = 1; off < 256; off <<= 1) {
        int v = (t >= off) ? sm[t - off] : 0;
        __syncthreads();
        sm[t] += v;
        __syncthreads();
    }
    int run = g_partx[b] + sm[t] - myv;
    #pragma unroll
    for (int i = 0; i < 4; ++i) {
        if (base + i < N_NODES) {
            g_rowptr[base + i] = run;
            g_cursor[base + i] = run;
        }
        run += d[i];
    }
}

__global__ void place_kernel() {
    int e = blockIdx.x * blockDim.x + threadIdx.x;
    if (e >= N_EDGES) return;
    int dgt = g_dst[e];
    int pos = atomicAdd(&g_cursor[dgt], 1);
    g_csr[pos] = g_src[e];
}

// ---------------------------------------------------------------------------
// Gather: Z[v] = Y[v] + sum_{(u->v)} Y[u].  16 threads per node (float4 cols).
// ---------------------------------------------------------------------------
__global__ __launch_bounds__(256) void gather_kernel(const float* __restrict__ Y,
                                                     float* __restrict__ Z) {
    long long t = (long long)blockIdx.x * blockDim.x + threadIdx.x;
    if (t >= (long long)N_NODES * 16) return;
    int node = (int)(t >> 4);
    int c    = (int)(t & 15) * 4;
    int lo = g_rowptr[node], hi = g_rowptr[node + 1];
    float4 acc = *(const float4*)&Y[(size_t)node * 64 + c];
    for (int i = lo; i < hi; ++i) {
        int s = g_csr[i];
        float4 v = *(const float4*)&Y[(size_t)s * 64 + c];
        acc.x += v.x; acc.y += v.y; acc.z += v.z; acc.w += v.w;
    }
    *(float4*)&Z[(size_t)node * 64 + c] = acc;
}

// ---------------------------------------------------------------------------
// mma over one BK=32 chunk; A raw in smem (split at read, optional bias+relu);
// W pre-split hi/lo planes in smem (pure LDS, no cvt).
// ---------------------------------------------------------------------------
template<bool BIAS>
__device__ __forceinline__ void mma_pre_chunk(const float* __restrict__ Ab,
                                              const float* __restrict__ Wh,
                                              const float* __restrict__ Wl,
                                              const float* __restrict__ ba, int k0,
                                              float c[2][4][4],
                                              int wrow, int wcol, int g, int tg) {
    #pragma unroll
    for (int kk = 0; kk < 32; kk += 8) {
        float ba0 = 0.f, ba1 = 0.f;
        if (BIAS) {
            ba0 = __ldg(&ba[k0 + kk + tg]);
            ba1 = __ldg(&ba[k0 + kk + tg + 4]);
        }
        unsigned ah[2][4], al[2][4];
        #pragma unroll
        for (int i = 0; i < 2; ++i) {
            int r0 = wrow + 16 * i + g;
            float a0 = Ab[(r0    ) * AS_STR + kk + tg];
            float a1 = Ab[(r0 + 8) * AS_STR + kk + tg];
            float a2 = Ab[(r0    ) * AS_STR + kk + tg + 4];
            float a3 = Ab[(r0 + 8) * AS_STR + kk + tg + 4];
            if (BIAS) {
                a0 = fmaxf(a0 + ba0, 0.f); a1 = fmaxf(a1 + ba0, 0.f);
                a2 = fmaxf(a2 + ba1, 0.f); a3 = fmaxf(a3 + ba1, 0.f);
            }
            split2(a0, ah[i][0], al[i][0]);
            split2(a1, ah[i][1], al[i][1]);
            split2(a2, ah[i][2], al[i][2]);
            split2(a3, ah[i][3], al[i][3]);
        }
        #pragma unroll
        for (int j = 0; j < 4; ++j) {
            int cc = wcol + 8 * j + g;
            unsigned bh0 = __float_as_uint(Wh[(kk + tg    ) * WS_STR + cc]);
            unsigned bh1 = __float_as_uint(Wh[(kk + tg + 4) * WS_STR + cc]);
            unsigned bl0 = __float_as_uint(Wl[(kk + tg    ) * WS_STR + cc]);
            unsigned bl1 = __float_as_uint(Wl[(kk + tg + 4) * WS_STR + cc]);
            #pragma unroll
            for (int i = 0; i < 2; ++i) {
                mma_tf32(c[i][j][0], c[i][j][1], c[i][j][2], c[i][j][3],
                         al[i][0], al[i][1], al[i][2], al[i][3], bh0, bh1);
                mma_tf32(c[i][j][0], c[i][j][1], c[i][j][2], c[i][j][3],
                         ah[i][0], ah[i][1], ah[i][2], ah[i][3], bl0, bl1);
                mma_tf32(c[i][j][0], c[i][j][1], c[i][j][2], c[i][j][3],
                         ah[i][0], ah[i][1], ah[i][2], ah[i][3], bh0, bh1);
            }
        }
    }
}

// raw-W variant (mm_first only: W split at read)
__device__ __forceinline__ void mma_raw_chunk(const float* __restrict__ Ab,
                                              const float* __restrict__ Wk,
                                              float c[2][4][4],
                                              int wrow, int wcol, int g, int tg) {
    #pragma unroll
    for (int kk = 0; kk < 32; kk += 8) {
        unsigned ah[2][4], al[2][4];
        #pragma unroll
        for (int i = 0; i < 2; ++i) {
            int r0 = wrow + 16 * i + g;
            split2(Ab[(r0    ) * AS_STR + kk + tg],     ah[i][0], al[i][0]);
            split2(Ab[(r0 + 8) * AS_STR + kk + tg],     ah[i][1], al[i][1]);
            split2(Ab[(r0    ) * AS_STR + kk + tg + 4], ah[i][2], al[i][2]);
            split2(Ab[(r0 + 8) * AS_STR + kk + tg + 4], ah[i][3], al[i][3]);
        }
        #pragma unroll
        for (int j = 0; j < 4; ++j) {
            int cc = wcol + 8 * j + g;
            unsigned bh0, bl0, bh1, bl1;
            split2(Wk[(kk + tg    ) * WS_STR + cc], bh0, bl0);
            split2(Wk[(kk + tg + 4) * WS_STR + cc], bh1, bl1);
            #pragma unroll
            for (int i = 0; i < 2; ++i) {
                mma_tf32(c[i][j][0], c[i][j][1], c[i][j][2], c[i][j][3],
                         al[i][0], al[i][1], al[i][2], al[i][3], bh0, bh1);
                mma_tf32(c[i][j][0], c[i][j][1], c[i][j][2], c[i][j][3],
                         ah[i][0], ah[i][1], ah[i][2], ah[i][3], bl0, bl1);
                mma_tf32(c[i][j][0], c[i][j][1], c[i][j][2], c[i][j][3],
                         ah[i][0], ah[i][1], ah[i][2], ah[i][3], bh0, bh1);
            }
        }
    }
}

template<int K>
__device__ __forceinline__ void cp_chunk(float* Ab, const float* __restrict__ A,
                                         int rowBase, int ch, int tid) {
    #pragma unroll
    for (int s = 0; s < 4; ++s) {
        int idx = tid + s * 256;
        int row = idx >> 3;
        int kg  = (idx & 7) * 4;
        int gr  = rowBase + row;
        cp16(&Ab[(size_t)(ch * 128 + row) * AS_STR + kg],
             &A[(size_t)gr * K + ch * 32 + kg], gr < N_NODES);
    }
    cp_commit();
}

__device__ __forceinline__ void load_w_all(float* Ws, const float* __restrict__ W,
                                           int K, int tid) {
    for (int idx = tid; idx < K * 16; idx += 256) {
        int k  = idx >> 4;
        int cg = (idx & 15) * 4;
        *(float4*)&Ws[(size_t)k * WS_STR + cg] = *(const float4*)&W[(size_t)k * 64 + cg];
    }
}

// ---------------------------------------------------------------------------
// mm_first: Y = A[N,K] @ W[K,64]   (raw W, split at read)
// ---------------------------------------------------------------------------
template<int K>
__global__ __launch_bounds__(256, 2) void mm_first(const float* __restrict__ A,
                                                   const float* __restrict__ W,
                                                   float* __restrict__ Y) {
    constexpr int NCH = K / 32;
    extern __shared__ float sm[];
    float* Ab = sm;
    float* Ws = sm + (size_t)NCH * 128 * AS_STR;

    const int tid  = threadIdx.x;
    const int lane = tid & 31;
    const int w    = tid >> 5;
    const int g    = lane >> 2;
    const int tg   = lane & 3;
    const int wrow = (w & 3) * 32;
    const int wcol = (w >> 2) * 32;
    const int rowBase = blockIdx.x * 128;
    float c[2][4][4] = {};

    load_w_all(Ws, W, K, tid);
    #pragma unroll
    for (int ch = 0; ch < NCH; ++ch)
        cp_chunk<K>(Ab, A, rowBase, ch, tid);

    #pragma unroll
    for (int ch = 0; ch < NCH; ++ch) {
        cp_wait(NCH - 1 - ch);
        __syncthreads();
        mma_raw_chunk(Ab + (size_t)ch * 128 * AS_STR,
                      Ws + (size_t)ch * 32 * WS_STR, c, wrow, wcol, g, tg);
    }

    #pragma unroll
    for (int i = 0; i < 2; ++i) {
        int r0 = rowBase + wrow + 16 * i + g;
        #pragma unroll
        for (int j = 0; j < 4; ++j) {
            int col = wcol + 8 * j + 2 * tg;
            if (r0 < N_NODES)
                *(float2*)&Y[(size_t)r0 * 64 + col] = make_float2(c[i][j][0], c[i][j][1]);
            if (r0 + 8 < N_NODES)
                *(float2*)&Y[(size_t)(r0 + 8) * 64 + col] = make_float2(c[i][j][2], c[i][j][3]);
        }
    }
}

// ---------------------------------------------------------------------------
// mm_chain: T = relu(relu(Z+ba) @ Wb + bb);  Yn = T @ Wa2.
// Wb/Wa2 hi-lo planes come pre-split from g_wh/g_wl (offsets mb, ma).
// ---------------------------------------------------------------------------
__global__ __launch_bounds__(256, 2) void mm_chain(const float* __restrict__ Z,
                                                   const float* __restrict__ ba,
                                                   const float* __restrict__ bbv,
                                                   int mb, int ma,
                                                   float* __restrict__ Yn) {
    extern __shared__ float sm[];
    float* Ab  = sm;                                  // 2*128*AS_STR
    float* WbH = sm  + (size_t)2 * 128 * AS_STR;      // 64*WS_STR each
    float* WbL = WbH + (size_t)64 * WS_STR;
    float* WaH = WbL + (size_t)64 * WS_STR;
    float* WaL = WaH + (size_t)64 * WS_STR;

    const int tid  = threadIdx.x;
    const int lane = tid & 31;
    const int w    = tid >> 5;
    const int g    = lane >> 2;
    const int tg   = lane & 3;
    const int wrow = (w & 3) * 32;
    const int wcol = (w >> 2) * 32;
    const int rowBase = blockIdx.x * 128;
    float c[2][4][4] = {};

    load_w_all(WbH, g_wh + (size_t)mb * 4096, 64, tid);
    load_w_all(WbL, g_wl + (size_t)mb * 4096, 64, tid);
    load_w_all(WaH, g_wh + (size_t)ma * 4096, 64, tid);
    load_w_all(WaL, g_wl + (size_t)ma * 4096, 64, tid);
    cp_chunk<64>(Ab, Z, rowBase, 0, tid);
    cp_chunk<64>(Ab, Z, rowBase, 1, tid);

    // GEMM1: relu(Z+ba) @ Wb
    cp_wait(1); __syncthreads();
    mma_pre_chunk<true>(Ab, WbH, WbL, ba, 0, c, wrow, wcol, g, tg);
    cp_wait(0); __syncthreads();
    mma_pre_chunk<true>(Ab + (size_t)128 * AS_STR,
                        WbH + (size_t)32 * WS_STR, WbL + (size_t)32 * WS_STR,
                        ba, 32, c, wrow, wcol, g, tg);
    __syncthreads();   // A-buffers free

    // stage T = relu(c+bb) raw into A-buffer (chunk = warp's wcol group)
    {
        float* Tb = Ab + (size_t)(wcol >> 5) * 128 * AS_STR;
        #pragma unroll
        for (int i = 0; i < 2; ++i) {
            int ra = wrow + 16 * i + g;
            #pragma unroll
            for (int j = 0; j < 4; ++j) {
                int lc = 8 * j + 2 * tg;
                float2 b2 = __ldg((const float2*)&bbv[wcol + lc]);
                *(float2*)&Tb[(size_t)ra * AS_STR + lc] =
                    make_float2(fmaxf(c[i][j][0] + b2.x, 0.f),
                                fmaxf(c[i][j][1] + b2.y, 0.f));
                *(float2*)&Tb[(size_t)(ra + 8) * AS_STR + lc] =
                    make_float2(fmaxf(c[i][j][2] + b2.x, 0.f),
                                fmaxf(c[i][j][3] + b2.y, 0.f));
                c[i][j][0] = c[i][j][1] = c[i][j][2] = c[i][j][3] = 0.f;
            }
        }
    }
    __syncthreads();

    // GEMM2: T @ Wa2
    mma_pre_chunk<false>(Ab, WaH, WaL, nullptr, 0, c, wrow, wcol, g, tg);
    mma_pre_chunk<false>(Ab + (size_t)128 * AS_STR,
                         WaH + (size_t)32 * WS_STR, WaL + (size_t)32 * WS_STR,
                         nullptr, 0, c, wrow, wcol, g, tg);

    #pragma unroll
    for (int i = 0; i < 2; ++i) {
        int r0 = rowBase + wrow + 16 * i + g;
        #pragma unroll
        for (int j = 0; j < 4; ++j) {
            int col = wcol + 8 * j + 2 * tg;
            if (r0 < N_NODES)
                *(float2*)&Yn[(size_t)r0 * 64 + col] = make_float2(c[i][j][0], c[i][j][1]);
            if (r0 + 8 < N_NODES)
                *(float2*)&Yn[(size_t)(r0 + 8) * 64 + col] = make_float2(c[i][j][2], c[i][j][3]);
        }
    }
}

// ---------------------------------------------------------------------------
// mm_last: H = relu(relu(Z+ba) @ Wb + bb)   (Wb pre-split, offset mb)
// ---------------------------------------------------------------------------
__global__ __launch_bounds__(256, 2) void mm_last(const float* __restrict__ Z,
                                                  const float* __restrict__ ba,
                                                  const float* __restrict__ bbv,
                                                  int mb,
                                                  float* __restrict__ H) {
    extern __shared__ float sm[];
    float* Ab  = sm;
    float* WbH = sm  + (size_t)2 * 128 * AS_STR;
    float* WbL = WbH + (size_t)64 * WS_STR;

    const int tid  = threadIdx.x;
    const int lane = tid & 31;
    const int w    = tid >> 5;
    const int g    = lane >> 2;
    const int tg   = lane & 3;
    const int wrow = (w & 3) * 32;
    const int wcol = (w >> 2) * 32;
    const int rowBase = blockIdx.x * 128;
    float c[2][4][4] = {};

    load_w_all(WbH, g_wh + (size_t)mb * 4096, 64, tid);
    load_w_all(WbL, g_wl + (size_t)mb * 4096, 64, tid);
    cp_chunk<64>(Ab, Z, rowBase, 0, tid);
    cp_chunk<64>(Ab, Z, rowBase, 1, tid);

    cp_wait(1); __syncthreads();
    mma_pre_chunk<true>(Ab, WbH, WbL, ba, 0, c, wrow, wcol, g, tg);
    cp_wait(0); __syncthreads();
    mma_pre_chunk<true>(Ab + (size_t)128 * AS_STR,
                        WbH + (size_t)32 * WS_STR, WbL + (size_t)32 * WS_STR,
                        ba, 32, c, wrow, wcol, g, tg);

    #pragma unroll
    for (int i = 0; i < 2; ++i) {
        int r0 = rowBase + wrow + 16 * i + g;
        #pragma unroll
        for (int j = 0; j < 4; ++j) {
            int col = wcol + 8 * j + 2 * tg;
            float2 b2 = __ldg((const float2*)&bbv[col]);
            if (r0 < N_NODES)
                *(float2*)&H[(size_t)r0 * 64 + col] =
                    make_float2(fmaxf(c[i][j][0] + b2.x, 0.f),
                                fmaxf(c[i][j][1] + b2.y, 0.f));
            if (r0 + 8 < N_NODES)
                *(float2*)&H[(size_t)(r0 + 8) * 64 + col] =
                    make_float2(fmaxf(c[i][j][2] + b2.x, 0.f),
                                fmaxf(c[i][j][3] + b2.y, 0.f));
        }
    }
}

// ---------------------------------------------------------------------------
// Head: per-graph pooled sum + MLP.  One 64-thread block per graph.
// ---------------------------------------------------------------------------
__global__ __launch_bounds__(64) void head_kernel(const float* __restrict__ H,
                                                  const float* __restrict__ wh1,
                                                  const float* __restrict__ bh1,
                                                  const float* __restrict__ wh2,
                                                  const float* __restrict__ bh2,
                                                  float* __restrict__ out) {
    const int g = blockIdx.x;
    const int tid = threadIdx.x;
    __shared__ float pooled[64];
    __shared__ float red[64];
    __shared__ int range[2];
    if (tid < 2) {
        int target = g + tid;
        int lo = 0, hi = N_NODES;
        while (lo < hi) {
            int mid = (lo + hi) >> 1;
            if (g_batch[mid] < target) lo = mid + 1; else hi = mid;
        }
        range[tid] = lo;
    }
    __syncthreads();
    const int lo = range[0], hi = range[1];
    float p = 0.f;
    for (int i = lo; i < hi; ++i) p += H[(size_t)i * 64 + tid];
    pooled[tid] = p;
    __syncthreads();
    float u = bh1[tid];
    #pragma unroll
    for (int k = 0; k < 64; ++k) u += pooled[k] * wh1[k * 64 + tid];
    u = fmaxf(u, 0.f);
    red[tid] = u * wh2[tid];
    __syncthreads();
    if (tid < 32) red[tid] += red[tid + 32];
    __syncthreads();
    if (tid < 32) {
        float v = red[tid];
        #pragma unroll
        for (int off = 16; off; off >>= 1)
            v += __shfl_down_sync(0xffffffffu, v, off);
        if (tid == 0) out[g] = v + bh2[0];
    }
}

// ---------------------------------------------------------------------------
extern "C" void kernel_launch(void* const* d_in, const int* in_sizes, int n_in,
                              void* d_out, int out_size) {
    const float* x    = (const float*)d_in[0];
    const void*  edge = d_in[1];
    const void*  batc = d_in[2];
    const float* w0a = (const float*)d_in[3];
    const float* b0a = (const float*)d_in[4];
    const float* w0b = (const float*)d_in[5];
    const float* b0b = (const float*)d_in[6];
    const float* w1a = (const float*)d_in[7];
    const float* b1a = (const float*)d_in[8];
    const float* w1b = (const float*)d_in[9];
    const float* b1b = (const float*)d_in[10];
    const float* w2a = (const float*)d_in[11];
    const float* b2a = (const float*)d_in[12];
    const float* w2b = (const float*)d_in[13];
    const float* b2b = (const float*)d_in[14];
    const float* wh1 = (const float*)d_in[15];
    const float* bh1 = (const float*)d_in[16];
    const float* wh2 = (const float*)d_in[17];
    const float* bh2 = (const float*)d_in[18];

    float *yb, *zb, *hb;
    int  *curb;
    cudaGetSymbolAddress((void**)&yb,   g_y);
    cudaGetSymbolAddress((void**)&zb,   g_z);
    cudaGetSymbolAddress((void**)&hb,   g_h);
    cudaGetSymbolAddress((void**)&curb, g_cursor);

    const int smFirst = (4 * 128 * AS_STR + 128 * WS_STR) * 4;     // 110592
    const int smChain = (2 * 128 * AS_STR + 4 * 64 * WS_STR) * 4;  // 110592
    const int smLast  = (2 * 128 * AS_STR + 2 * 64 * WS_STR) * 4;  //  73728
    cudaFuncSetAttribute(mm_first<128>, cudaFuncAttributeMaxDynamicSharedMemorySize, smFirst);
    cudaFuncSetAttribute(mm_chain,      cudaFuncAttributeMaxDynamicSharedMemorySize, smChain);
    cudaFuncSetAttribute(mm_last,       cudaFuncAttributeMaxDynamicSharedMemorySize, smLast);

    // side stream + events for graph-captured parallel branch (created once;
    // creation is a host-side resource, not device memory)
    static cudaStream_t s2 = nullptr;
    static cudaEvent_t evFork = nullptr, evJoin = nullptr;
    if (!s2) {
        cudaStreamCreateWithFlags(&s2, cudaStreamNonBlocking);
        cudaEventCreateWithFlags(&evFork, cudaEventDisableTiming);
        cudaEventCreateWithFlags(&evJoin, cudaEventDisableTiming);
    }

    const int mmGrid   = (N_NODES + 127) / 128;
    const int gatGrid  = (int)(((long long)N_NODES * 16 + 255) / 256);
    const int edgGrid  = (N_EDGES + 255) / 256;

    // ---- fork: side branch does prep + wsplit + CSR build while the main
    //      branch runs mm_first (independent: needs only x, w0a) ----
    cudaEventRecord(evFork, 0);
    cudaStreamWaitEvent(s2, evFork, 0);

    prep_kernel<<<edgGrid, 256, 0, s2>>>(edge, batc);
    wsplit_kernel<<<(5 * 4096 + 255) / 256, 256, 0, s2>>>(w0b, w1a, w1b, w2a, w2b);
    cudaMemsetAsync(curb, 0, (size_t)N_NODES * sizeof(int), s2);
    hist_kernel<<<edgGrid, 256, 0, s2>>>();
    scan1_kernel<<<NB, 256, 0, s2>>>();
    scan2_kernel<<<1, 512, 0, s2>>>();
    scan3_kernel<<<NB, 256, 0, s2>>>();
    place_kernel<<<edgGrid, 256, 0, s2>>>();
    cudaEventRecord(evJoin, s2);

    // main branch: y0 = x @ w0a
    mm_first<128><<<mmGrid, 256, smFirst>>>(x, w0a, yb);

    // join before first gather (needs CSR + prep results)
    cudaStreamWaitEvent(0, evJoin, 0);

    // layer 0: z = gather(y); chain -> y1  (w0b = idx0, w1a = idx1)
    gather_kernel<<<gatGrid, 256>>>(yb, zb);
    mm_chain<<<mmGrid, 256, smChain>>>(zb, b0a, b0b, 0, 1, yb);

    // layer 1: (w1b = idx2, w2a = idx3)
    gather_kernel<<<gatGrid, 256>>>(yb, zb);
    mm_chain<<<mmGrid, 256, smChain>>>(zb, b1a, b1b, 2, 3, yb);

    // layer 2: (w2b = idx4)
    gather_kernel<<<gatGrid, 256>>>(yb, zb);
    mm_last<<<mmGrid, 256, smLast>>>(zb, b2a, b2b, 4, hb);

    head_kernel<<<N_GRAPHS, 64>>>(hb, wh1, bh1, wh2, bh2, (float*)d_out);
}

// round 16
// speedup vs baseline: 1.1174x; 1.0195x over previous
#include <cuda_runtime.h>
#include <cstdint>

#define N_NODES 500000
#define N_EDGES 1250000
#define IN_DIM  128
#define HID     64
#define N_GRAPHS 16384

#define AS_STR 36   // A plane stride (floats): frag bank = 4g+tg, conflict-free
#define WS_STR 72   // W plane stride (floats): frag bank = 8tg+g, conflict-free

#define SCH 1024
#define NB ((N_NODES + SCH - 1) / SCH)   // 489 scan blocks

// ---- scratch (static device globals: allocation-free rule) ----
__device__ float g_y  [(size_t)N_NODES * HID];   // y = h @ wa
__device__ float g_z  [(size_t)N_NODES * HID];   // z = y + agg (gather output)
__device__ float g_h  [(size_t)N_NODES * HID];   // final layer output
__device__ int   g_src[N_EDGES];
__device__ int   g_dst[N_EDGES];
__device__ int   g_batch[N_NODES];
__device__ int   g_rowptr[N_NODES + 1];
__device__ int   g_cursor[N_NODES];
__device__ int   g_csr[N_EDGES];
__device__ int   g_part[512];
__device__ int   g_partx[512];
__device__ float g_wh[5 * 64 * 64];              // pre-split W hi planes
__device__ float g_wl[5 * 64 * 64];              // pre-split W lo planes

// ---------------------------------------------------------------------------
// helpers
// ---------------------------------------------------------------------------
__device__ __forceinline__ float f2tf32(float x) {
    unsigned r;
    asm("cvt.rna.tf32.f32 %0, %1;" : "=r"(r) : "f"(x));
    return __uint_as_float(r);
}
__device__ __forceinline__ void split2(float x, unsigned& hi, unsigned& lo) {
    float h = f2tf32(x);
    float l = f2tf32(x - h);
    hi = __float_as_uint(h);
    lo = __float_as_uint(l);
}
__device__ __forceinline__ void mma_tf32(float& c0, float& c1, float& c2, float& c3,
                                         unsigned a0, unsigned a1, unsigned a2, unsigned a3,
                                         unsigned b0, unsigned b1) {
    asm volatile("mma.sync.aligned.m16n8k8.row.col.f32.tf32.tf32.f32 "
                 "{%0,%1,%2,%3}, {%4,%5,%6,%7}, {%8,%9}, {%0,%1,%2,%3};"
                 : "+f"(c0), "+f"(c1), "+f"(c2), "+f"(c3)
                 : "r"(a0), "r"(a1), "r"(a2), "r"(a3), "r"(b0), "r"(b1));
}
__device__ __forceinline__ void cp16(float* dst_smem, const float* src, bool pred) {
    unsigned d = (unsigned)__cvta_generic_to_shared(dst_smem);
    int sz = pred ? 16 : 0;
    asm volatile("cp.async.cg.shared.global [%0], [%1], 16, %2;"
                 :: "r"(d), "l"(src), "r"(sz));
}
__device__ __forceinline__ void cp_commit() { asm volatile("cp.async.commit_group;"); }
__device__ __forceinline__ void cp_wait(int n) {
    switch (n) {
        case 0: asm volatile("cp.async.wait_group 0;"); break;
        case 1: asm volatile("cp.async.wait_group 1;"); break;
        case 2: asm volatile("cp.async.wait_group 2;"); break;
        default: asm volatile("cp.async.wait_group 3;"); break;
    }
}

// ---------------------------------------------------------------------------
// prep: detect int32 vs int64 indices, convert to int32 scratch.
// Word (N_NODES-1) is ODD: int64 layout -> high half = 0; int32 -> max gid != 0.
// ---------------------------------------------------------------------------
__global__ void prep_kernel(const void* __restrict__ edge,
                            const void* __restrict__ batch) {
    const bool mode64 = (((const int*)batch)[N_NODES - 1] == 0);
    int t = blockIdx.x * blockDim.x + threadIdx.x;
    if (t < N_EDGES) {
        if (mode64) {
            g_src[t] = (int)((const long long*)edge)[t];
            g_dst[t] = (int)((const long long*)edge)[N_EDGES + t];
        } else {
            g_src[t] = ((const int*)edge)[t];
            g_dst[t] = ((const int*)edge)[N_EDGES + t];
        }
    }
    if (t < N_NODES) {
        g_batch[t] = mode64 ? (int)((const long long*)batch)[t]
                            : ((const int*)batch)[t];
    }
}

// ---- W pre-split: 5 matrices (w0b, w1a, w1b, w2a, w2b), each 64x64 --------
__global__ void wsplit_kernel(const float* __restrict__ w0b,
                              const float* __restrict__ w1a,
                              const float* __restrict__ w1b,
                              const float* __restrict__ w2a,
                              const float* __restrict__ w2b) {
    int t = blockIdx.x * blockDim.x + threadIdx.x;
    if (t >= 5 * 4096) return;
    int m = t >> 12, i = t & 4095;
    const float* W = (m == 0) ? w0b : (m == 1) ? w1a : (m == 2) ? w1b
                   : (m == 3) ? w2a : w2b;
    float x = W[i];
    float h = f2tf32(x);
    g_wh[t] = h;
    g_wl[t] = f2tf32(x - h);
}

// ---------------------------------------------------------------------------
// CSR build: histogram -> hierarchical exclusive scan -> placement.
// ---------------------------------------------------------------------------
__global__ void hist_kernel() {
    int e = blockIdx.x * blockDim.x + threadIdx.x;
    if (e < N_EDGES) atomicAdd(&g_cursor[g_dst[e]], 1);
}

__global__ __launch_bounds__(256) void scan1_kernel() {
    __shared__ int sm[256];
    int b = blockIdx.x, t = threadIdx.x;
    int base = b * SCH + t * 4;
    int s = 0;
    #pragma unroll
    for (int i = 0; i < 4; ++i)
        if (base + i < N_NODES) s += g_cursor[base + i];
    sm[t] = s;
    __syncthreads();
    for (int off = 128; off; off >>= 1) {
        if (t < off) sm[t] += sm[t + off];
        __syncthreads();
    }
    if (t == 0) g_part[b] = sm[0];
}

__global__ __launch_bounds__(512) void scan2_kernel() {
    __shared__ int sm[512];
    int t = threadIdx.x;
    int myv = (t < NB) ? g_part[t] : 0;
    sm[t] = myv;
    __syncthreads();
    for (int off = 1; off < 512; off <<= 1) {
        int v = (t >= off) ? sm[t - off] : 0;
        __syncthreads();
        sm[t] += v;
        __syncthreads();
    }
    if (t < NB) g_partx[t] = sm[t] - myv;     // exclusive
    if (t == 0) g_rowptr[N_NODES] = N_EDGES;
}

__global__ __launch_bounds__(256) void scan3_kernel() {
    __shared__ int sm[256];
    int b = blockIdx.x, t = threadIdx.x;
    int base = b * SCH + t * 4;
    int d[4];
    int s = 0;
    #pragma unroll
    for (int i = 0; i < 4; ++i) {
        d[i] = (base + i < N_NODES) ? g_cursor[base + i] : 0;
        s += d[i];
    }
    int myv = s;
    sm[t] = s;
    __syncthreads();
    for (int off = 1; off < 256; off <<= 1) {
        int v = (t >= off) ? sm[t - off] : 0;
        __syncthreads();
        sm[t] += v;
        __syncthreads();
    }
    int run = g_partx[b] + sm[t] - myv;
    #pragma unroll
    for (int i = 0; i < 4; ++i) {
        if (base + i < N_NODES) {
            g_rowptr[base + i] = run;
            g_cursor[base + i] = run;
        }
        run += d[i];
    }
}

__global__ void place_kernel() {
    int e = blockIdx.x * blockDim.x + threadIdx.x;
    if (e >= N_EDGES) return;
    int dgt = g_dst[e];
    int pos = atomicAdd(&g_cursor[dgt], 1);
    g_csr[pos] = g_src[e];
}

// ---------------------------------------------------------------------------
// Gather: Z[v] = Y[v] + sum_{(u->v)} Y[u].  16 threads per node (float4 cols).
// ---------------------------------------------------------------------------
__global__ __launch_bounds__(256) void gather_kernel(const float* __restrict__ Y,
                                                     float* __restrict__ Z) {
    long long t = (long long)blockIdx.x * blockDim.x + threadIdx.x;
    if (t >= (long long)N_NODES * 16) return;
    int node = (int)(t >> 4);
    int c    = (int)(t & 15) * 4;
    int lo = g_rowptr[node], hi = g_rowptr[node + 1];
    float4 acc = *(const float4*)&Y[(size_t)node * 64 + c];
    for (int i = lo; i < hi; ++i) {
        int s = g_csr[i];
        float4 v = *(const float4*)&Y[(size_t)s * 64 + c];
        acc.x += v.x; acc.y += v.y; acc.z += v.z; acc.w += v.w;
    }
    *(float4*)&Z[(size_t)node * 64 + c] = acc;
}

// ---------------------------------------------------------------------------
// mma over one BK=32 chunk; A raw in smem (split at read, optional bias+relu);
// W pre-split hi/lo planes in smem (pure LDS, no cvt).
// ---------------------------------------------------------------------------
template<bool BIAS>
__device__ __forceinline__ void mma_pre_chunk(const float* __restrict__ Ab,
                                              const float* __restrict__ Wh,
                                              const float* __restrict__ Wl,
                                              const float* __restrict__ ba, int k0,
                                              float c[2][4][4],
                                              int wrow, int wcol, int g, int tg) {
    #pragma unroll
    for (int kk = 0; kk < 32; kk += 8) {
        float ba0 = 0.f, ba1 = 0.f;
        if (BIAS) {
            ba0 = __ldg(&ba[k0 + kk + tg]);
            ba1 = __ldg(&ba[k0 + kk + tg + 4]);
        }
        unsigned ah[2][4], al[2][4];
        #pragma unroll
        for (int i = 0; i < 2; ++i) {
            int r0 = wrow + 16 * i + g;
            float a0 = Ab[(r0    ) * AS_STR + kk + tg];
            float a1 = Ab[(r0 + 8) * AS_STR + kk + tg];
            float a2 = Ab[(r0    ) * AS_STR + kk + tg + 4];
            float a3 = Ab[(r0 + 8) * AS_STR + kk + tg + 4];
            if (BIAS) {
                a0 = fmaxf(a0 + ba0, 0.f); a1 = fmaxf(a1 + ba0, 0.f);
                a2 = fmaxf(a2 + ba1, 0.f); a3 = fmaxf(a3 + ba1, 0.f);
            }
            split2(a0, ah[i][0], al[i][0]);
            split2(a1, ah[i][1], al[i][1]);
            split2(a2, ah[i][2], al[i][2]);
            split2(a3, ah[i][3], al[i][3]);
        }
        #pragma unroll
        for (int j = 0; j < 4; ++j) {
            int cc = wcol + 8 * j + g;
            unsigned bh0 = __float_as_uint(Wh[(kk + tg    ) * WS_STR + cc]);
            unsigned bh1 = __float_as_uint(Wh[(kk + tg + 4) * WS_STR + cc]);
            unsigned bl0 = __float_as_uint(Wl[(kk + tg    ) * WS_STR + cc]);
            unsigned bl1 = __float_as_uint(Wl[(kk + tg + 4) * WS_STR + cc]);
            #pragma unroll
            for (int i = 0; i < 2; ++i) {
                mma_tf32(c[i][j][0], c[i][j][1], c[i][j][2], c[i][j][3],
                         al[i][0], al[i][1], al[i][2], al[i][3], bh0, bh1);
                mma_tf32(c[i][j][0], c[i][j][1], c[i][j][2], c[i][j][3],
                         ah[i][0], ah[i][1], ah[i][2], ah[i][3], bl0, bl1);
                mma_tf32(c[i][j][0], c[i][j][1], c[i][j][2], c[i][j][3],
                         ah[i][0], ah[i][1], ah[i][2], ah[i][3], bh0, bh1);
            }
        }
    }
}

// raw-W variant (mm_first only: W split at read)
__device__ __forceinline__ void mma_raw_chunk(const float* __restrict__ Ab,
                                              const float* __restrict__ Wk,
                                              float c[2][4][4],
                                              int wrow, int wcol, int g, int tg) {
    #pragma unroll
    for (int kk = 0; kk < 32; kk += 8) {
        unsigned ah[2][4], al[2][4];
        #pragma unroll
        for (int i = 0; i < 2; ++i) {
            int r0 = wrow + 16 * i + g;
            split2(Ab[(r0    ) * AS_STR + kk + tg],     ah[i][0], al[i][0]);
            split2(Ab[(r0 + 8) * AS_STR + kk + tg],     ah[i][1], al[i][1]);
            split2(Ab[(r0    ) * AS_STR + kk + tg + 4], ah[i][2], al[i][2]);
            split2(Ab[(r0 + 8) * AS_STR + kk + tg + 4], ah[i][3], al[i][3]);
        }
        #pragma unroll
        for (int j = 0; j < 4; ++j) {
            int cc = wcol + 8 * j + g;
            unsigned bh0, bl0, bh1, bl1;
            split2(Wk[(kk + tg    ) * WS_STR + cc], bh0, bl0);
            split2(Wk[(kk + tg + 4) * WS_STR + cc], bh1, bl1);
            #pragma unroll
            for (int i = 0; i < 2; ++i) {
                mma_tf32(c[i][j][0], c[i][j][1], c[i][j][2], c[i][j][3],
                         al[i][0], al[i][1], al[i][2], al[i][3], bh0, bh1);
                mma_tf32(c[i][j][0], c[i][j][1], c[i][j][2], c[i][j][3],
                         ah[i][0], ah[i][1], ah[i][2], ah[i][3], bl0, bl1);
                mma_tf32(c[i][j][0], c[i][j][1], c[i][j][2], c[i][j][3],
                         ah[i][0], ah[i][1], ah[i][2], ah[i][3], bh0, bh1);
            }
        }
    }
}

template<int K>
__device__ __forceinline__ void cp_chunk(float* Ab, const float* __restrict__ A,
                                         int rowBase, int ch, int tid) {
    #pragma unroll
    for (int s = 0; s < 4; ++s) {
        int idx = tid + s * 256;
        int row = idx >> 3;
        int kg  = (idx & 7) * 4;
        int gr  = rowBase + row;
        cp16(&Ab[(size_t)(ch * 128 + row) * AS_STR + kg],
             &A[(size_t)gr * K + ch * 32 + kg], gr < N_NODES);
    }
    cp_commit();
}

__device__ __forceinline__ void load_w_all(float* Ws, const float* __restrict__ W,
                                           int K, int tid) {
    for (int idx = tid; idx < K * 16; idx += 256) {
        int k  = idx >> 4;
        int cg = (idx & 15) * 4;
        *(float4*)&Ws[(size_t)k * WS_STR + cg] = *(const float4*)&W[(size_t)k * 64 + cg];
    }
}

// ---------------------------------------------------------------------------
// mm_first: Y = A[N,K] @ W[K,64]   (raw W, split at read)
// ---------------------------------------------------------------------------
template<int K>
__global__ __launch_bounds__(256, 2) void mm_first(const float* __restrict__ A,
                                                   const float* __restrict__ W,
                                                   float* __restrict__ Y) {
    constexpr int NCH = K / 32;
    extern __shared__ float sm[];
    float* Ab = sm;
    float* Ws = sm + (size_t)NCH * 128 * AS_STR;

    const int tid  = threadIdx.x;
    const int lane = tid & 31;
    const int w    = tid >> 5;
    const int g    = lane >> 2;
    const int tg   = lane & 3;
    const int wrow = (w & 3) * 32;
    const int wcol = (w >> 2) * 32;
    const int rowBase = blockIdx.x * 128;
    float c[2][4][4] = {};

    load_w_all(Ws, W, K, tid);
    #pragma unroll
    for (int ch = 0; ch < NCH; ++ch)
        cp_chunk<K>(Ab, A, rowBase, ch, tid);

    #pragma unroll
    for (int ch = 0; ch < NCH; ++ch) {
        cp_wait(NCH - 1 - ch);
        __syncthreads();
        mma_raw_chunk(Ab + (size_t)ch * 128 * AS_STR,
                      Ws + (size_t)ch * 32 * WS_STR, c, wrow, wcol, g, tg);
    }

    #pragma unroll
    for (int i = 0; i < 2; ++i) {
        int r0 = rowBase + wrow + 16 * i + g;
        #pragma unroll
        for (int j = 0; j < 4; ++j) {
            int col = wcol + 8 * j + 2 * tg;
            if (r0 < N_NODES)
                *(float2*)&Y[(size_t)r0 * 64 + col] = make_float2(c[i][j][0], c[i][j][1]);
            if (r0 + 8 < N_NODES)
                *(float2*)&Y[(size_t)(r0 + 8) * 64 + col] = make_float2(c[i][j][2], c[i][j][3]);
        }
    }
}

// ---------------------------------------------------------------------------
// mm_chain: T = relu(relu(Z+ba) @ Wb + bb);  Yn = T @ Wa2.
// Single reusable W region (36 KB): Wb planes for GEMM1 are overwritten with
// Wa planes during the T-staging barrier window.  smem 73.7 KB -> 3 CTAs/SM.
// ---------------------------------------------------------------------------
__global__ __launch_bounds__(256, 3) void mm_chain(const float* __restrict__ Z,
                                                   const float* __restrict__ ba,
                                                   const float* __restrict__ bbv,
                                                   int mb, int ma,
                                                   float* __restrict__ Yn) {
    extern __shared__ float sm[];
    float* Ab = sm;                                  // 2*128*AS_STR
    float* WH = sm + (size_t)2 * 128 * AS_STR;       // 64*WS_STR
    float* WL = WH + (size_t)64 * WS_STR;            // 64*WS_STR

    const int tid  = threadIdx.x;
    const int lane = tid & 31;
    const int w    = tid >> 5;
    const int g    = lane >> 2;
    const int tg   = lane & 3;
    const int wrow = (w & 3) * 32;
    const int wcol = (w >> 2) * 32;
    const int rowBase = blockIdx.x * 128;
    float c[2][4][4] = {};

    load_w_all(WH, g_wh + (size_t)mb * 4096, 64, tid);
    load_w_all(WL, g_wl + (size_t)mb * 4096, 64, tid);
    cp_chunk<64>(Ab, Z, rowBase, 0, tid);
    cp_chunk<64>(Ab, Z, rowBase, 1, tid);

    // GEMM1: relu(Z+ba) @ Wb
    cp_wait(1); __syncthreads();
    mma_pre_chunk<true>(Ab, WH, WL, ba, 0, c, wrow, wcol, g, tg);
    cp_wait(0); __syncthreads();
    mma_pre_chunk<true>(Ab + (size_t)128 * AS_STR,
                        WH + (size_t)32 * WS_STR, WL + (size_t)32 * WS_STR,
                        ba, 32, c, wrow, wcol, g, tg);
    __syncthreads();   // A-buffers + W region free (all GEMM1 reads done)

    // stage T = relu(c+bb) into A-buffer; simultaneously reload W region with Wa
    {
        float* Tb = Ab + (size_t)(wcol >> 5) * 128 * AS_STR;
        #pragma unroll
        for (int i = 0; i < 2; ++i) {
            int ra = wrow + 16 * i + g;
            #pragma unroll
            for (int j = 0; j < 4; ++j) {
                int lc = 8 * j + 2 * tg;
                float2 b2 = __ldg((const float2*)&bbv[wcol + lc]);
                *(float2*)&Tb[(size_t)ra * AS_STR + lc] =
                    make_float2(fmaxf(c[i][j][0] + b2.x, 0.f),
                                fmaxf(c[i][j][1] + b2.y, 0.f));
                *(float2*)&Tb[(size_t)(ra + 8) * AS_STR + lc] =
                    make_float2(fmaxf(c[i][j][2] + b2.x, 0.f),
                                fmaxf(c[i][j][3] + b2.y, 0.f));
                c[i][j][0] = c[i][j][1] = c[i][j][2] = c[i][j][3] = 0.f;
            }
        }
        load_w_all(WH, g_wh + (size_t)ma * 4096, 64, tid);
        load_w_all(WL, g_wl + (size_t)ma * 4096, 64, tid);
    }
    __syncthreads();

    // GEMM2: T @ Wa2
    mma_pre_chunk<false>(Ab, WH, WL, nullptr, 0, c, wrow, wcol, g, tg);
    mma_pre_chunk<false>(Ab + (size_t)128 * AS_STR,
                         WH + (size_t)32 * WS_STR, WL + (size_t)32 * WS_STR,
                         nullptr, 0, c, wrow, wcol, g, tg);

    #pragma unroll
    for (int i = 0; i < 2; ++i) {
        int r0 = rowBase + wrow + 16 * i + g;
        #pragma unroll
        for (int j = 0; j < 4; ++j) {
            int col = wcol + 8 * j + 2 * tg;
            if (r0 < N_NODES)
                *(float2*)&Yn[(size_t)r0 * 64 + col] = make_float2(c[i][j][0], c[i][j][1]);
            if (r0 + 8 < N_NODES)
                *(float2*)&Yn[(size_t)(r0 + 8) * 64 + col] = make_float2(c[i][j][2], c[i][j][3]);
        }
    }
}

// ---------------------------------------------------------------------------
// mm_last: H = relu(relu(Z+ba) @ Wb + bb)   (Wb pre-split, offset mb)
// ---------------------------------------------------------------------------
__global__ __launch_bounds__(256, 3) void mm_last(const float* __restrict__ Z,
                                                  const float* __restrict__ ba,
                                                  const float* __restrict__ bbv,
                                                  int mb,
                                                  float* __restrict__ H) {
    extern __shared__ float sm[];
    float* Ab = sm;
    float* WH = sm + (size_t)2 * 128 * AS_STR;
    float* WL = WH + (size_t)64 * WS_STR;

    const int tid  = threadIdx.x;
    const int lane = tid & 31;
    const int w    = tid >> 5;
    const int g    = lane >> 2;
    const int tg   = lane & 3;
    const int wrow = (w & 3) * 32;
    const int wcol = (w >> 2) * 32;
    const int rowBase = blockIdx.x * 128;
    float c[2][4][4] = {};

    load_w_all(WH, g_wh + (size_t)mb * 4096, 64, tid);
    load_w_all(WL, g_wl + (size_t)mb * 4096, 64, tid);
    cp_chunk<64>(Ab, Z, rowBase, 0, tid);
    cp_chunk<64>(Ab, Z, rowBase, 1, tid);

    cp_wait(1); __syncthreads();
    mma_pre_chunk<true>(Ab, WH, WL, ba, 0, c, wrow, wcol, g, tg);
    cp_wait(0); __syncthreads();
    mma_pre_chunk<true>(Ab + (size_t)128 * AS_STR,
                        WH + (size_t)32 * WS_STR, WL + (size_t)32 * WS_STR,
                        ba, 32, c, wrow, wcol, g, tg);

    #pragma unroll
    for (int i = 0; i < 2; ++i) {
        int r0 = rowBase + wrow + 16 * i + g;
        #pragma unroll
        for (int j = 0; j < 4; ++j) {
            int col = wcol + 8 * j + 2 * tg;
            float2 b2 = __ldg((const float2*)&bbv[col]);
            if (r0 < N_NODES)
                *(float2*)&H[(size_t)r0 * 64 + col] =
                    make_float2(fmaxf(c[i][j][0] + b2.x, 0.f),
                                fmaxf(c[i][j][1] + b2.y, 0.f));
            if (r0 + 8 < N_NODES)
                *(float2*)&H[(size_t)(r0 + 8) * 64 + col] =
                    make_float2(fmaxf(c[i][j][2] + b2.x, 0.f),
                                fmaxf(c[i][j][3] + b2.y, 0.f));
        }
    }
}

// ---------------------------------------------------------------------------
// Head: per-graph pooled sum + MLP.  One 64-thread block per graph.
// ---------------------------------------------------------------------------
__global__ __launch_bounds__(64) void head_kernel(const float* __restrict__ H,
                                                  const float* __restrict__ wh1,
                                                  const float* __restrict__ bh1,
                                                  const float* __restrict__ wh2,
                                                  const float* __restrict__ bh2,
                                                  float* __restrict__ out) {
    const int g = blockIdx.x;
    const int tid = threadIdx.x;
    __shared__ float pooled[64];
    __shared__ float red[64];
    __shared__ int range[2];
    if (tid < 2) {
        int target = g + tid;
        int lo = 0, hi = N_NODES;
        while (lo < hi) {
            int mid = (lo + hi) >> 1;
            if (g_batch[mid] < target) lo = mid + 1; else hi = mid;
        }
        range[tid] = lo;
    }
    __syncthreads();
    const int lo = range[0], hi = range[1];
    float p = 0.f;
    for (int i = lo; i < hi; ++i) p += H[(size_t)i * 64 + tid];
    pooled[tid] = p;
    __syncthreads();
    float u = bh1[tid];
    #pragma unroll
    for (int k = 0; k < 64; ++k) u += pooled[k] * wh1[k * 64 + tid];
    u = fmaxf(u, 0.f);
    red[tid] = u * wh2[tid];
    __syncthreads();
    if (tid < 32) red[tid] += red[tid + 32];
    __syncthreads();
    if (tid < 32) {
        float v = red[tid];
        #pragma unroll
        for (int off = 16; off; off >>= 1)
            v += __shfl_down_sync(0xffffffffu, v, off);
        if (tid == 0) out[g] = v + bh2[0];
    }
}

// ---------------------------------------------------------------------------
extern "C" void kernel_launch(void* const* d_in, const int* in_sizes, int n_in,
                              void* d_out, int out_size) {
    const float* x    = (const float*)d_in[0];
    const void*  edge = d_in[1];
    const void*  batc = d_in[2];
    const float* w0a = (const float*)d_in[3];
    const float* b0a = (const float*)d_in[4];
    const float* w0b = (const float*)d_in[5];
    const float* b0b = (const float*)d_in[6];
    const float* w1a = (const float*)d_in[7];
    const float* b1a = (const float*)d_in[8];
    const float* w1b = (const float*)d_in[9];
    const float* b1b = (const float*)d_in[10];
    const float* w2a = (const float*)d_in[11];
    const float* b2a = (const float*)d_in[12];
    const float* w2b = (const float*)d_in[13];
    const float* b2b = (const float*)d_in[14];
    const float* wh1 = (const float*)d_in[15];
    const float* bh1 = (const float*)d_in[16];
    const float* wh2 = (const float*)d_in[17];
    const float* bh2 = (const float*)d_in[18];

    float *yb, *zb, *hb;
    int  *curb;
    cudaGetSymbolAddress((void**)&yb,   g_y);
    cudaGetSymbolAddress((void**)&zb,   g_z);
    cudaGetSymbolAddress((void**)&hb,   g_h);
    cudaGetSymbolAddress((void**)&curb, g_cursor);

    const int smFirst = (4 * 128 * AS_STR + 128 * WS_STR) * 4;     // 110592
    const int smChain = (2 * 128 * AS_STR + 2 * 64 * WS_STR) * 4;  //  73728
    const int smLast  = smChain;                                   //  73728
    cudaFuncSetAttribute(mm_first<128>, cudaFuncAttributeMaxDynamicSharedMemorySize, smFirst);
    cudaFuncSetAttribute(mm_chain,      cudaFuncAttributeMaxDynamicSharedMemorySize, smChain);
    cudaFuncSetAttribute(mm_last,       cudaFuncAttributeMaxDynamicSharedMemorySize, smLast);

    const int mmGrid   = (N_NODES + 127) / 128;
    const int gatGrid  = (int)(((long long)N_NODES * 16 + 255) / 256);
    const int edgGrid  = (N_EDGES + 255) / 256;

    prep_kernel<<<edgGrid, 256>>>(edge, batc);
    wsplit_kernel<<<(5 * 4096 + 255) / 256, 256>>>(w0b, w1a, w1b, w2a, w2b);

    // CSR build
    cudaMemsetAsync(curb, 0, (size_t)N_NODES * sizeof(int));
    hist_kernel<<<edgGrid, 256>>>();
    scan1_kernel<<<NB, 256>>>();
    scan2_kernel<<<1, 512>>>();
    scan3_kernel<<<NB, 256>>>();
    place_kernel<<<edgGrid, 256>>>();

    // y0 = x @ w0a
    mm_first<128><<<mmGrid, 256, smFirst>>>(x, w0a, yb);

    // layer 0: z = gather(y); chain -> y1  (w0b = idx0, w1a = idx1)
    gather_kernel<<<gatGrid, 256>>>(yb, zb);
    mm_chain<<<mmGrid, 256, smChain>>>(zb, b0a, b0b, 0, 1, yb);

    // layer 1: (w1b = idx2, w2a = idx3)
    gather_kernel<<<gatGrid, 256>>>(yb, zb);
    mm_chain<<<mmGrid, 256, smChain>>>(zb, b1a, b1b, 2, 3, yb);

    // layer 2: (w2b = idx4)
    gather_kernel<<<gatGrid, 256>>>(yb, zb);
    mm_last<<<mmGrid, 256, smLast>>>(zb, b2a, b2b, 4, hb);

    head_kernel<<<N_GRAPHS, 64>>>(hb, wh1, bh1, wh2, bh2, (float*)d_out);
}

// round 17
// speedup vs baseline: 1.1302x; 1.0114x over previous
#include <cuda_runtime.h>
#include <cstdint>

#define N_NODES 500000
#define N_EDGES 1250000
#define IN_DIM  128
#define HID     64
#define N_GRAPHS 16384

#define AS_STR 36   // A plane stride (floats): frag bank = 4g+tg, conflict-free
#define WS_STR 72   // W plane stride (floats): frag bank = 8tg+g, conflict-free

#define SCH 1024
#define NB ((N_NODES + SCH - 1) / SCH)   // 489 scan blocks

// ---- scratch (static device globals: allocation-free rule) ----
__device__ float g_y  [(size_t)N_NODES * HID];   // y = h @ wa
__device__ float g_z  [(size_t)N_NODES * HID];   // z = y + agg (gather output)
__device__ float g_h  [(size_t)N_NODES * HID];   // final layer output
__device__ int   g_src[N_EDGES];
__device__ int   g_dst[N_EDGES];
__device__ int   g_batch[N_NODES];
__device__ int   g_rowptr[N_NODES + 1];
__device__ int   g_cursor[N_NODES];
__device__ int   g_csr[N_EDGES];
__device__ int   g_part[512];
__device__ int   g_partx[512];
__device__ float g_wh[5 * 64 * 64];              // pre-split W hi planes
__device__ float g_wl[5 * 64 * 64];              // pre-split W lo planes

// ---------------------------------------------------------------------------
// helpers
// ---------------------------------------------------------------------------
__device__ __forceinline__ float f2tf32(float x) {
    unsigned r;
    asm("cvt.rna.tf32.f32 %0, %1;" : "=r"(r) : "f"(x));
    return __uint_as_float(r);
}
__device__ __forceinline__ void split2(float x, unsigned& hi, unsigned& lo) {
    float h = f2tf32(x);
    float l = f2tf32(x - h);
    hi = __float_as_uint(h);
    lo = __float_as_uint(l);
}
__device__ __forceinline__ void mma_tf32(float& c0, float& c1, float& c2, float& c3,
                                         unsigned a0, unsigned a1, unsigned a2, unsigned a3,
                                         unsigned b0, unsigned b1) {
    asm volatile("mma.sync.aligned.m16n8k8.row.col.f32.tf32.tf32.f32 "
                 "{%0,%1,%2,%3}, {%4,%5,%6,%7}, {%8,%9}, {%0,%1,%2,%3};"
                 : "+f"(c0), "+f"(c1), "+f"(c2), "+f"(c3)
                 : "r"(a0), "r"(a1), "r"(a2), "r"(a3), "r"(b0), "r"(b1));
}
__device__ __forceinline__ void cp16(float* dst_smem, const float* src, bool pred) {
    unsigned d = (unsigned)__cvta_generic_to_shared(dst_smem);
    int sz = pred ? 16 : 0;
    asm volatile("cp.async.cg.shared.global [%0], [%1], 16, %2;"
                 :: "r"(d), "l"(src), "r"(sz));
}
__device__ __forceinline__ void cp_commit() { asm volatile("cp.async.commit_group;"); }
__device__ __forceinline__ void cp_wait(int n) {
    switch (n) {
        case 0: asm volatile("cp.async.wait_group 0;"); break;
        case 1: asm volatile("cp.async.wait_group 1;"); break;
        case 2: asm volatile("cp.async.wait_group 2;"); break;
        default: asm volatile("cp.async.wait_group 3;"); break;
    }
}

// ---------------------------------------------------------------------------
// prep+hist fused: detect int32 vs int64 indices, convert to int32 scratch,
// and accumulate the destination-degree histogram in the same edge sweep.
// Word (N_NODES-1) is ODD: int64 layout -> high half = 0; int32 -> max gid != 0.
// g_cursor must be zeroed before this kernel.
// ---------------------------------------------------------------------------
__global__ void prep_hist_kernel(const void* __restrict__ edge,
                                 const void* __restrict__ batch) {
    const bool mode64 = (((const int*)batch)[N_NODES - 1] == 0);
    int t = blockIdx.x * blockDim.x + threadIdx.x;
    if (t < N_EDGES) {
        int s, d;
        if (mode64) {
            s = (int)((const long long*)edge)[t];
            d = (int)((const long long*)edge)[N_EDGES + t];
        } else {
            s = ((const int*)edge)[t];
            d = ((const int*)edge)[N_EDGES + t];
        }
        g_src[t] = s;
        g_dst[t] = d;
        atomicAdd(&g_cursor[d], 1);
    }
    if (t < N_NODES) {
        g_batch[t] = mode64 ? (int)((const long long*)batch)[t]
                            : ((const int*)batch)[t];
    }
}

// ---- W pre-split: 5 matrices (w0b, w1a, w1b, w2a, w2b), each 64x64 --------
__global__ void wsplit_kernel(const float* __restrict__ w0b,
                              const float* __restrict__ w1a,
                              const float* __restrict__ w1b,
                              const float* __restrict__ w2a,
                              const float* __restrict__ w2b) {
    int t = blockIdx.x * blockDim.x + threadIdx.x;
    if (t >= 5 * 4096) return;
    int m = t >> 12, i = t & 4095;
    const float* W = (m == 0) ? w0b : (m == 1) ? w1a : (m == 2) ? w1b
                   : (m == 3) ? w2a : w2b;
    float x = W[i];
    float h = f2tf32(x);
    g_wh[t] = h;
    g_wl[t] = f2tf32(x - h);
}

// ---------------------------------------------------------------------------
// CSR build: (histogram fused into prep) -> hierarchical scan -> placement.
// ---------------------------------------------------------------------------
__global__ __launch_bounds__(256) void scan1_kernel() {
    __shared__ int sm[256];
    int b = blockIdx.x, t = threadIdx.x;
    int base = b * SCH + t * 4;
    int s = 0;
    #pragma unroll
    for (int i = 0; i < 4; ++i)
        if (base + i < N_NODES) s += g_cursor[base + i];
    sm[t] = s;
    __syncthreads();
    for (int off = 128; off; off >>= 1) {
        if (t < off) sm[t] += sm[t + off];
        __syncthreads();
    }
    if (t == 0) g_part[b] = sm[0];
}

__global__ __launch_bounds__(512) void scan2_kernel() {
    __shared__ int sm[512];
    int t = threadIdx.x;
    int myv = (t < NB) ? g_part[t] : 0;
    sm[t] = myv;
    __syncthreads();
    for (int off = 1; off < 512; off <<= 1) {
        int v = (t >= off) ? sm[t - off] : 0;
        __syncthreads();
        sm[t] += v;
        __syncthreads();
    }
    if (t < NB) g_partx[t] = sm[t] - myv;     // exclusive
    if (t == 0) g_rowptr[N_NODES] = N_EDGES;
}

__global__ __launch_bounds__(256) void scan3_kernel() {
    __shared__ int sm[256];
    int b = blockIdx.x, t = threadIdx.x;
    int base = b * SCH + t * 4;
    int d[4];
    int s = 0;
    #pragma unroll
    for (int i = 0; i < 4; ++i) {
        d[i] = (base + i < N_NODES) ? g_cursor[base + i] : 0;
        s += d[i];
    }
    int myv = s;
    sm[t] = s;
    __syncthreads();
    for (int off = 1; off < 256; off <<= 1) {
        int v = (t >= off) ? sm[t - off] : 0;
        __syncthreads();
        sm[t] += v;
        __syncthreads();
    }
    int run = g_partx[b] + sm[t] - myv;
    #pragma unroll
    for (int i = 0; i < 4; ++i) {
        if (base + i < N_NODES) {
            g_rowptr[base + i] = run;
            g_cursor[base + i] = run;
        }
        run += d[i];
    }
}

__global__ void place_kernel() {
    int e = blockIdx.x * blockDim.x + threadIdx.x;
    if (e >= N_EDGES) return;
    int dgt = g_dst[e];
    int pos = atomicAdd(&g_cursor[dgt], 1);
    g_csr[pos] = g_src[e];
}

// ---------------------------------------------------------------------------
// Gather: Z[v] = Y[v] + sum_{(u->v)} Y[u].  16 threads per node (float4 cols).
// ---------------------------------------------------------------------------
__global__ __launch_bounds__(256) void gather_kernel(const float* __restrict__ Y,
                                                     float* __restrict__ Z) {
    long long t = (long long)blockIdx.x * blockDim.x + threadIdx.x;
    if (t >= (long long)N_NODES * 16) return;
    int node = (int)(t >> 4);
    int c    = (int)(t & 15) * 4;
    int lo = g_rowptr[node], hi = g_rowptr[node + 1];
    float4 acc = *(const float4*)&Y[(size_t)node * 64 + c];
    for (int i = lo; i < hi; ++i) {
        int s = g_csr[i];
        float4 v = *(const float4*)&Y[(size_t)s * 64 + c];
        acc.x += v.x; acc.y += v.y; acc.z += v.z; acc.w += v.w;
    }
    *(float4*)&Z[(size_t)node * 64 + c] = acc;
}

// ---------------------------------------------------------------------------
// mma over one BK=32 chunk; A raw in smem (split at read, optional bias+relu);
// W pre-split hi/lo planes in smem (pure LDS, no cvt).
// ---------------------------------------------------------------------------
template<bool BIAS>
__device__ __forceinline__ void mma_pre_chunk(const float* __restrict__ Ab,
                                              const float* __restrict__ Wh,
                                              const float* __restrict__ Wl,
                                              const float* __restrict__ ba, int k0,
                                              float c[2][4][4],
                                              int wrow, int wcol, int g, int tg) {
    #pragma unroll
    for (int kk = 0; kk < 32; kk += 8) {
        float ba0 = 0.f, ba1 = 0.f;
        if (BIAS) {
            ba0 = __ldg(&ba[k0 + kk + tg]);
            ba1 = __ldg(&ba[k0 + kk + tg + 4]);
        }
        unsigned ah[2][4], al[2][4];
        #pragma unroll
        for (int i = 0; i < 2; ++i) {
            int r0 = wrow + 16 * i + g;
            float a0 = Ab[(r0    ) * AS_STR + kk + tg];
            float a1 = Ab[(r0 + 8) * AS_STR + kk + tg];
            float a2 = Ab[(r0    ) * AS_STR + kk + tg + 4];
            float a3 = Ab[(r0 + 8) * AS_STR + kk + tg + 4];
            if (BIAS) {
                a0 = fmaxf(a0 + ba0, 0.f); a1 = fmaxf(a1 + ba0, 0.f);
                a2 = fmaxf(a2 + ba1, 0.f); a3 = fmaxf(a3 + ba1, 0.f);
            }
            split2(a0, ah[i][0], al[i][0]);
            split2(a1, ah[i][1], al[i][1]);
            split2(a2, ah[i][2], al[i][2]);
            split2(a3, ah[i][3], al[i][3]);
        }
        #pragma unroll
        for (int j = 0; j < 4; ++j) {
            int cc = wcol + 8 * j + g;
            unsigned bh0 = __float_as_uint(Wh[(kk + tg    ) * WS_STR + cc]);
            unsigned bh1 = __float_as_uint(Wh[(kk + tg + 4) * WS_STR + cc]);
            unsigned bl0 = __float_as_uint(Wl[(kk + tg    ) * WS_STR + cc]);
            unsigned bl1 = __float_as_uint(Wl[(kk + tg + 4) * WS_STR + cc]);
            #pragma unroll
            for (int i = 0; i < 2; ++i) {
                mma_tf32(c[i][j][0], c[i][j][1], c[i][j][2], c[i][j][3],
                         al[i][0], al[i][1], al[i][2], al[i][3], bh0, bh1);
                mma_tf32(c[i][j][0], c[i][j][1], c[i][j][2], c[i][j][3],
                         ah[i][0], ah[i][1], ah[i][2], ah[i][3], bl0, bl1);
                mma_tf32(c[i][j][0], c[i][j][1], c[i][j][2], c[i][j][3],
                         ah[i][0], ah[i][1], ah[i][2], ah[i][3], bh0, bh1);
            }
        }
    }
}

// raw-W variant (mm_first only: W split at read)
__device__ __forceinline__ void mma_raw_chunk(const float* __restrict__ Ab,
                                              const float* __restrict__ Wk,
                                              float c[2][4][4],
                                              int wrow, int wcol, int g, int tg) {
    #pragma unroll
    for (int kk = 0; kk < 32; kk += 8) {
        unsigned ah[2][4], al[2][4];
        #pragma unroll
        for (int i = 0; i < 2; ++i) {
            int r0 = wrow + 16 * i + g;
            split2(Ab[(r0    ) * AS_STR + kk + tg],     ah[i][0], al[i][0]);
            split2(Ab[(r0 + 8) * AS_STR + kk + tg],     ah[i][1], al[i][1]);
            split2(Ab[(r0    ) * AS_STR + kk + tg + 4], ah[i][2], al[i][2]);
            split2(Ab[(r0 + 8) * AS_STR + kk + tg + 4], ah[i][3], al[i][3]);
        }
        #pragma unroll
        for (int j = 0; j < 4; ++j) {
            int cc = wcol + 8 * j + g;
            unsigned bh0, bl0, bh1, bl1;
            split2(Wk[(kk + tg    ) * WS_STR + cc], bh0, bl0);
            split2(Wk[(kk + tg + 4) * WS_STR + cc], bh1, bl1);
            #pragma unroll
            for (int i = 0; i < 2; ++i) {
                mma_tf32(c[i][j][0], c[i][j][1], c[i][j][2], c[i][j][3],
                         al[i][0], al[i][1], al[i][2], al[i][3], bh0, bh1);
                mma_tf32(c[i][j][0], c[i][j][1], c[i][j][2], c[i][j][3],
                         ah[i][0], ah[i][1], ah[i][2], ah[i][3], bl0, bl1);
                mma_tf32(c[i][j][0], c[i][j][1], c[i][j][2], c[i][j][3],
                         ah[i][0], ah[i][1], ah[i][2], ah[i][3], bh0, bh1);
            }
        }
    }
}

// issue cp.async of 32-column source chunk srcCh into the given A buffer
template<int K>
__device__ __forceinline__ void cp_chunk(float* AbBuf, const float* __restrict__ A,
                                         int rowBase, int srcCh, int tid) {
    #pragma unroll
    for (int s = 0; s < 4; ++s) {
        int idx = tid + s * 256;
        int row = idx >> 3;
        int kg  = (idx & 7) * 4;
        int gr  = rowBase + row;
        cp16(&AbBuf[(size_t)row * AS_STR + kg],
             &A[(size_t)gr * K + srcCh * 32 + kg], gr < N_NODES);
    }
    cp_commit();
}

__device__ __forceinline__ void load_w_all(float* Ws, const float* __restrict__ W,
                                           int K, int tid) {
    for (int idx = tid; idx < K * 16; idx += 256) {
        int k  = idx >> 4;
        int cg = (idx & 15) * 4;
        *(float4*)&Ws[(size_t)k * WS_STR + cg] = *(const float4*)&W[(size_t)k * 64 + cg];
    }
}

// ---------------------------------------------------------------------------
// mm_first: Y = A[N,K] @ W[K,64]  (raw W, split at read).
// Double-buffered A pipeline: 2 x 18 KB A bufs + 36 KB W = 73.7 KB -> 3 CTAs/SM.
// ---------------------------------------------------------------------------
template<int K>
__global__ __launch_bounds__(256, 3) void mm_first(const float* __restrict__ A,
                                                   const float* __restrict__ W,
                                                   float* __restrict__ Y) {
    constexpr int NCH = K / 32;
    extern __shared__ float sm[];
    float* Ab0 = sm;
    float* Ab1 = sm + (size_t)128 * AS_STR;
    float* Ws  = sm + (size_t)2 * 128 * AS_STR;

    const int tid  = threadIdx.x;
    const int lane = tid & 31;
    const int w    = tid >> 5;
    const int g    = lane >> 2;
    const int tg   = lane & 3;
    const int wrow = (w & 3) * 32;
    const int wcol = (w >> 2) * 32;
    const int rowBase = blockIdx.x * 128;
    float c[2][4][4] = {};

    load_w_all(Ws, W, K, tid);
    cp_chunk<K>(Ab0, A, rowBase, 0, tid);
    if (NCH > 1) cp_chunk<K>(Ab1, A, rowBase, 1, tid);

    #pragma unroll
    for (int ch = 0; ch < NCH; ++ch) {
        float* buf = (ch & 1) ? Ab1 : Ab0;
        cp_wait((ch < NCH - 1) ? 1 : 0);
        __syncthreads();
        mma_raw_chunk(buf, Ws + (size_t)ch * 32 * WS_STR, c, wrow, wcol, g, tg);
        if (ch + 2 < NCH) {
            __syncthreads();                       // all reads of buf done
            cp_chunk<K>(buf, A, rowBase, ch + 2, tid);
        }
    }

    #pragma unroll
    for (int i = 0; i < 2; ++i) {
        int r0 = rowBase + wrow + 16 * i + g;
        #pragma unroll
        for (int j = 0; j < 4; ++j) {
            int col = wcol + 8 * j + 2 * tg;
            if (r0 < N_NODES)
                *(float2*)&Y[(size_t)r0 * 64 + col] = make_float2(c[i][j][0], c[i][j][1]);
            if (r0 + 8 < N_NODES)
                *(float2*)&Y[(size_t)(r0 + 8) * 64 + col] = make_float2(c[i][j][2], c[i][j][3]);
        }
    }
}

// ---------------------------------------------------------------------------
// mm_chain: T = relu(relu(Z+ba) @ Wb + bb);  Yn = T @ Wa2.
// Single reusable W region; Wa planes reloaded during the T-staging window.
// smem 73.7 KB -> 3 CTAs/SM.
// ---------------------------------------------------------------------------
__global__ __launch_bounds__(256, 3) void mm_chain(const float* __restrict__ Z,
                                                   const float* __restrict__ ba,
                                                   const float* __restrict__ bbv,
                                                   int mb, int ma,
                                                   float* __restrict__ Yn) {
    extern __shared__ float sm[];
    float* Ab = sm;                                  // 2*128*AS_STR
    float* WH = sm + (size_t)2 * 128 * AS_STR;       // 64*WS_STR
    float* WL = WH + (size_t)64 * WS_STR;            // 64*WS_STR

    const int tid  = threadIdx.x;
    const int lane = tid & 31;
    const int w    = tid >> 5;
    const int g    = lane >> 2;
    const int tg   = lane & 3;
    const int wrow = (w & 3) * 32;
    const int wcol = (w >> 2) * 32;
    const int rowBase = blockIdx.x * 128;
    float c[2][4][4] = {};

    load_w_all(WH, g_wh + (size_t)mb * 4096, 64, tid);
    load_w_all(WL, g_wl + (size_t)mb * 4096, 64, tid);
    cp_chunk<64>(Ab, Z, rowBase, 0, tid);
    cp_chunk<64>(Ab + (size_t)128 * AS_STR, Z, rowBase, 1, tid);

    // GEMM1: relu(Z+ba) @ Wb
    cp_wait(1); __syncthreads();
    mma_pre_chunk<true>(Ab, WH, WL, ba, 0, c, wrow, wcol, g, tg);
    cp_wait(0); __syncthreads();
    mma_pre_chunk<true>(Ab + (size_t)128 * AS_STR,
                        WH + (size_t)32 * WS_STR, WL + (size_t)32 * WS_STR,
                        ba, 32, c, wrow, wcol, g, tg);
    __syncthreads();   // A-buffers + W region free (all GEMM1 reads done)

    // stage T = relu(c+bb) into A-buffer; simultaneously reload W region with Wa
    {
        float* Tb = Ab + (size_t)(wcol >> 5) * 128 * AS_STR;
        #pragma unroll
        for (int i = 0; i < 2; ++i) {
            int ra = wrow + 16 * i + g;
            #pragma unroll
            for (int j = 0; j < 4; ++j) {
                int lc = 8 * j + 2 * tg;
                float2 b2 = __ldg((const float2*)&bbv[wcol + lc]);
                *(float2*)&Tb[(size_t)ra * AS_STR + lc] =
                    make_float2(fmaxf(c[i][j][0] + b2.x, 0.f),
                                fmaxf(c[i][j][1] + b2.y, 0.f));
                *(float2*)&Tb[(size_t)(ra + 8) * AS_STR + lc] =
                    make_float2(fmaxf(c[i][j][2] + b2.x, 0.f),
                                fmaxf(c[i][j][3] + b2.y, 0.f));
                c[i][j][0] = c[i][j][1] = c[i][j][2] = c[i][j][3] = 0.f;
            }
        }
        load_w_all(WH, g_wh + (size_t)ma * 4096, 64, tid);
        load_w_all(WL, g_wl + (size_t)ma * 4096, 64, tid);
    }
    __syncthreads();

    // GEMM2: T @ Wa2
    mma_pre_chunk<false>(Ab, WH, WL, nullptr, 0, c, wrow, wcol, g, tg);
    mma_pre_chunk<false>(Ab + (size_t)128 * AS_STR,
                         WH + (size_t)32 * WS_STR, WL + (size_t)32 * WS_STR,
                         nullptr, 0, c, wrow, wcol, g, tg);

    #pragma unroll
    for (int i = 0; i < 2; ++i) {
        int r0 = rowBase + wrow + 16 * i + g;
        #pragma unroll
        for (int j = 0; j < 4; ++j) {
            int col = wcol + 8 * j + 2 * tg;
            if (r0 < N_NODES)
                *(float2*)&Yn[(size_t)r0 * 64 + col] = make_float2(c[i][j][0], c[i][j][1]);
            if (r0 + 8 < N_NODES)
                *(float2*)&Yn[(size_t)(r0 + 8) * 64 + col] = make_float2(c[i][j][2], c[i][j][3]);
        }
    }
}

// ---------------------------------------------------------------------------
// mm_last: H = relu(relu(Z+ba) @ Wb + bb)   (Wb pre-split, offset mb)
// ---------------------------------------------------------------------------
__global__ __launch_bounds__(256, 3) void mm_last(const float* __restrict__ Z,
                                                  const float* __restrict__ ba,
                                                  const float* __restrict__ bbv,
                                                  int mb,
                                                  float* __restrict__ H) {
    extern __shared__ float sm[];
    float* Ab = sm;
    float* WH = sm + (size_t)2 * 128 * AS_STR;
    float* WL = WH + (size_t)64 * WS_STR;

    const int tid  = threadIdx.x;
    const int lane = tid & 31;
    const int w    = tid >> 5;
    const int g    = lane >> 2;
    const int tg   = lane & 3;
    const int wrow = (w & 3) * 32;
    const int wcol = (w >> 2) * 32;
    const int rowBase = blockIdx.x * 128;
    float c[2][4][4] = {};

    load_w_all(WH, g_wh + (size_t)mb * 4096, 64, tid);
    load_w_all(WL, g_wl + (size_t)mb * 4096, 64, tid);
    cp_chunk<64>(Ab, Z, rowBase, 0, tid);
    cp_chunk<64>(Ab + (size_t)128 * AS_STR, Z, rowBase, 1, tid);

    cp_wait(1); __syncthreads();
    mma_pre_chunk<true>(Ab, WH, WL, ba, 0, c, wrow, wcol, g, tg);
    cp_wait(0); __syncthreads();
    mma_pre_chunk<true>(Ab + (size_t)128 * AS_STR,
                        WH + (size_t)32 * WS_STR, WL + (size_t)32 * WS_STR,
                        ba, 32, c, wrow, wcol, g, tg);

    #pragma unroll
    for (int i = 0; i < 2; ++i) {
        int r0 = rowBase + wrow + 16 * i + g;
        #pragma unroll
        for (int j = 0; j < 4; ++j) {
            int col = wcol + 8 * j + 2 * tg;
            float2 b2 = __ldg((const float2*)&bbv[col]);
            if (r0 < N_NODES)
                *(float2*)&H[(size_t)r0 * 64 + col] =
                    make_float2(fmaxf(c[i][j][0] + b2.x, 0.f),
                                fmaxf(c[i][j][1] + b2.y, 0.f));
            if (r0 + 8 < N_NODES)
                *(float2*)&H[(size_t)(r0 + 8) * 64 + col] =
                    make_float2(fmaxf(c[i][j][2] + b2.x, 0.f),
                                fmaxf(c[i][j][3] + b2.y, 0.f));
        }
    }
}

// ---------------------------------------------------------------------------
// Head: per-graph pooled sum + MLP.  One 64-thread block per graph.
// ---------------------------------------------------------------------------
__global__ __launch_bounds__(64) void head_kernel(const float* __restrict__ H,
                                                  const float* __restrict__ wh1,
                                                  const float* __restrict__ bh1,
                                                  const float* __restrict__ wh2,
                                                  const float* __restrict__ bh2,
                                                  float* __restrict__ out) {
    const int g = blockIdx.x;
    const int tid = threadIdx.x;
    __shared__ float pooled[64];
    __shared__ float red[64];
    __shared__ int range[2];
    if (tid < 2) {
        int target = g + tid;
        int lo = 0, hi = N_NODES;
        while (lo < hi) {
            int mid = (lo + hi) >> 1;
            if (g_batch[mid] < target) lo = mid + 1; else hi = mid;
        }
        range[tid] = lo;
    }
    __syncthreads();
    const int lo = range[0], hi = range[1];
    float p = 0.f;
    for (int i = lo; i < hi; ++i) p += H[(size_t)i * 64 + tid];
    pooled[tid] = p;
    __syncthreads();
    float u = bh1[tid];
    #pragma unroll
    for (int k = 0; k < 64; ++k) u += pooled[k] * wh1[k * 64 + tid];
    u = fmaxf(u, 0.f);
    red[tid] = u * wh2[tid];
    __syncthreads();
    if (tid < 32) red[tid] += red[tid + 32];
    __syncthreads();
    if (tid < 32) {
        float v = red[tid];
        #pragma unroll
        for (int off = 16; off; off >>= 1)
            v += __shfl_down_sync(0xffffffffu, v, off);
        if (tid == 0) out[g] = v + bh2[0];
    }
}

// ---------------------------------------------------------------------------
extern "C" void kernel_launch(void* const* d_in, const int* in_sizes, int n_in,
                              void* d_out, int out_size) {
    const float* x    = (const float*)d_in[0];
    const void*  edge = d_in[1];
    const void*  batc = d_in[2];
    const float* w0a = (const float*)d_in[3];
    const float* b0a = (const float*)d_in[4];
    const float* w0b = (const float*)d_in[5];
    const float* b0b = (const float*)d_in[6];
    const float* w1a = (const float*)d_in[7];
    const float* b1a = (const float*)d_in[8];
    const float* w1b = (const float*)d_in[9];
    const float* b1b = (const float*)d_in[10];
    const float* w2a = (const float*)d_in[11];
    const float* b2a = (const float*)d_in[12];
    const float* w2b = (const float*)d_in[13];
    const float* b2b = (const float*)d_in[14];
    const float* wh1 = (const float*)d_in[15];
    const float* bh1 = (const float*)d_in[16];
    const float* wh2 = (const float*)d_in[17];
    const float* bh2 = (const float*)d_in[18];

    float *yb, *zb, *hb;
    int  *curb;
    cudaGetSymbolAddress((void**)&yb,   g_y);
    cudaGetSymbolAddress((void**)&zb,   g_z);
    cudaGetSymbolAddress((void**)&hb,   g_h);
    cudaGetSymbolAddress((void**)&curb, g_cursor);

    const int smGemm = (2 * 128 * AS_STR + 2 * 64 * WS_STR) * 4;   // 73728 all three
    cudaFuncSetAttribute(mm_first<128>, cudaFuncAttributeMaxDynamicSharedMemorySize, smGemm);
    cudaFuncSetAttribute(mm_chain,      cudaFuncAttributeMaxDynamicSharedMemorySize, smGemm);
    cudaFuncSetAttribute(mm_last,       cudaFuncAttributeMaxDynamicSharedMemorySize, smGemm);

    const int mmGrid   = (N_NODES + 127) / 128;
    const int gatGrid  = (int)(((long long)N_NODES * 16 + 255) / 256);
    const int edgGrid  = (N_EDGES + 255) / 256;

    // zero cursor, then fused prep+hist (single edge sweep)
    cudaMemsetAsync(curb, 0, (size_t)N_NODES * sizeof(int));
    prep_hist_kernel<<<edgGrid, 256>>>(edge, batc);
    wsplit_kernel<<<(5 * 4096 + 255) / 256, 256>>>(w0b, w1a, w1b, w2a, w2b);

    // CSR build (scan -> placement)
    scan1_kernel<<<NB, 256>>>();
    scan2_kernel<<<1, 512>>>();
    scan3_kernel<<<NB, 256>>>();
    place_kernel<<<edgGrid, 256>>>();

    // y0 = x @ w0a
    mm_first<128><<<mmGrid, 256, smGemm>>>(x, w0a, yb);

    // layer 0: z = gather(y); chain -> y1  (w0b = idx0, w1a = idx1)
    gather_kernel<<<gatGrid, 256>>>(yb, zb);
    mm_chain<<<mmGrid, 256, smGemm>>>(zb, b0a, b0b, 0, 1, yb);

    // layer 1: (w1b = idx2, w2a = idx3)
    gather_kernel<<<gatGrid, 256>>>(yb, zb);
    mm_chain<<<mmGrid, 256, smGemm>>>(zb, b1a, b1b, 2, 3, yb);

    // layer 2: (w2b = idx4)
    gather_kernel<<<gatGrid, 256>>>(yb, zb);
    mm_last<<<mmGrid, 256, smGemm>>>(zb, b2a, b2b, 4, hb);

    head_kernel<<<N_GRAPHS, 64>>>(hb, wh1, bh1, wh2, bh2, (float*)d_out);
}